// round 1
// baseline (speedup 1.0000x reference)
#include <cuda_runtime.h>
#include <cstdint>

#define B     64
#define F     3000
#define FSH   80
#define L     240000
#define EMPH  0.97f
#define NT    (B*F)
#define DEPTH 16

// Scratch (static device arrays -- allocation-free per harness rules)
__device__ __align__(16) static float g_h [(size_t)NT*80];   //  61.4 MB impulse responses
__device__ __align__(16) static float g_ap[(size_t)NT*16];   //  combined taps a'[1..16]
__device__ __align__(16) static float g_T [(size_t)NT*256];  // 196.6 MB transition mats (transposed)
__device__ __align__(16) static float g_C [(size_t)NT*16];   //  ZSR tail (affine term)
__device__ __align__(16) static float g_S [(size_t)NT*16];   //  per-frame start states

// ---------------------------------------------------------------------------
// Kernel 1: per (batch,frame) -- combined taps a', impulse response h,
// transition matrix T (stored transposed T^t[q][i] = T[i][q]), affine term C.
// Combined filter: z[n] = e[n] - sum_{j=1..16} a'_j z[n-j],
//   a'_j = a_j - EMPH*a_{j-1}  (a_0 = 1, a_16 = 0)
// ---------------------------------------------------------------------------
__global__ void __launch_bounds__(128) k_prep(const float* __restrict__ e,
                                              const float* __restrict__ lpc)
{
    int tid = blockIdx.x*128 + threadIdx.x;
    if (tid >= NT) return;
    int b = tid / F;
    int f = tid - b*F;

    float av[16];
    const float4* a4 = reinterpret_cast<const float4*>(lpc + (size_t)tid*16);
#pragma unroll
    for (int j = 0; j < 4; j++) {
        float4 t = a4[j];
        av[4*j+0]=t.x; av[4*j+1]=t.y; av[4*j+2]=t.z; av[4*j+3]=t.w;
    }

    float ap[17];
    ap[1] = av[1] - EMPH;                 // a0 == 1 by construction
#pragma unroll
    for (int j = 2; j <= 15; j++) ap[j] = av[j] - EMPH*av[j-1];
    ap[16] = -EMPH*av[15];

    // impulse response of 1/A'(z), fully unrolled -> register resident
    float h[80];
    h[0] = 1.f;
#pragma unroll
    for (int m = 1; m < 80; m++) {
        float acc = 0.f;
#pragma unroll
        for (int j = 1; j <= 16; j++)
            if (j <= m) acc = fmaf(ap[j], h[m-j], acc);
        h[m] = -acc;
    }

    float4* hout = reinterpret_cast<float4*>(g_h + (size_t)tid*80);
#pragma unroll
    for (int m = 0; m < 80; m += 4) {
        float4 t; t.x=h[m]; t.y=h[m+1]; t.z=h[m+2]; t.w=h[m+3];
        hout[m>>2] = t;
    }
    float4* apout = reinterpret_cast<float4*>(g_ap + (size_t)tid*16);
#pragma unroll
    for (int j = 0; j < 16; j += 4) {
        float4 t; t.x=ap[j+1]; t.y=ap[j+2]; t.z=ap[j+3]; t.w=ap[j+4];
        apout[j>>2] = t;
    }

    // T[i][q] = -sum_{mm=0..15-q} h[79-i-mm] * a'[mm+q+1]
    // stored transposed: g_T[q*16+i] so pass-2 reads are conflict-free
    float4* Tout = reinterpret_cast<float4*>(g_T + (size_t)tid*256);
#pragma unroll
    for (int q = 0; q < 16; q++) {
#pragma unroll
        for (int i4 = 0; i4 < 16; i4 += 4) {
            float v[4];
#pragma unroll
            for (int k = 0; k < 4; k++) {
                int i = i4 + k;
                float acc = 0.f;
#pragma unroll
                for (int mm = 0; mm <= 15-q; mm++)
                    acc = fmaf(h[79-i-mm], ap[mm+q+1], acc);
                v[k] = -acc;
            }
            float4 t; t.x=v[0]; t.y=v[1]; t.z=v[2]; t.w=v[3];
            Tout[(q*16+i4)>>2] = t;
        }
    }

    // zero-state response to this frame's excitation; tail -> C_i = w[79-i]
    const float4* ef4 = reinterpret_cast<const float4*>(e + (size_t)b*L + (size_t)f*FSH);
    float wr[16];
#pragma unroll
    for (int j = 0; j < 16; j++) wr[j] = 0.f;
    float ev[4];
#pragma unroll
    for (int m = 0; m < 80; m++) {
        if ((m & 3) == 0) {
            float4 t = ef4[m>>2];
            ev[0]=t.x; ev[1]=t.y; ev[2]=t.z; ev[3]=t.w;
        }
        float acc = ev[m & 3];
#pragma unroll
        for (int j = 1; j <= 16; j++)
            if (j <= m) acc = fmaf(-ap[j], wr[(m-j) & 15], acc);
        wr[m & 15] = acc;
    }
    float4* Cout = reinterpret_cast<float4*>(g_C + (size_t)tid*16);
#pragma unroll
    for (int i = 0; i < 16; i += 4) {
        float4 t;
        t.x = wr[15-i]; t.y = wr[15-(i+1)]; t.z = wr[15-(i+2)]; t.w = wr[15-(i+3)];
        Cout[i>>2] = t;
    }
}

// ---------------------------------------------------------------------------
// Kernel 2: sequential state scan per batch: s_{f+1} = T_f s_f + c_f.
// One warp per batch; lane i owns row i of the matvec; state broadcast via
// shfl. T/C streamed through a DEPTH-deep cp.async ring (272 floats/frame).
// ---------------------------------------------------------------------------
__device__ __forceinline__ void scan_prefetch(uint32_t rbase, size_t fb, int f, int lane)
{
    if (f < F) {
        uint32_t slot = rbase + (uint32_t)(f & (DEPTH-1)) * 272u * 4u;
        const float* Tf = g_T + (fb + (size_t)f)*256;
        const float* Cf = g_C + (fb + (size_t)f)*16;
        asm volatile("cp.async.ca.shared.global [%0], [%1], 16;"
                     :: "r"(slot + (uint32_t)lane*16u), "l"(Tf + lane*4) : "memory");
        asm volatile("cp.async.ca.shared.global [%0], [%1], 16;"
                     :: "r"(slot + (uint32_t)(lane+32)*16u), "l"(Tf + (lane+32)*4) : "memory");
        if (lane < 4)
            asm volatile("cp.async.ca.shared.global [%0], [%1], 16;"
                         :: "r"(slot + 1024u + (uint32_t)lane*16u), "l"(Cf + lane*4) : "memory");
    }
    asm volatile("cp.async.commit_group;" ::: "memory");
}

__global__ void __launch_bounds__(32) k_scan()
{
    __shared__ __align__(16) float ring[DEPTH][272];
    int b = blockIdx.x;
    int lane = threadIdx.x;
    size_t fb = (size_t)b * F;
    uint32_t rbase = (uint32_t)__cvta_generic_to_shared(&ring[0][0]);

#pragma unroll 1
    for (int f = 0; f < DEPTH; f++) scan_prefetch(rbase, fb, f, lane);

    float s = 0.f;                       // lane i (<16) holds state s_i
    float* Sout = g_S + fb*16;

#pragma unroll 1
    for (int f = 0; f < F; f++) {
        asm volatile("cp.async.wait_group 15;" ::: "memory");
        __syncwarp();
        const float* slotp = &ring[f & (DEPTH-1)][0];

        if (lane < 16) Sout[(size_t)f*16 + lane] = s;   // state at frame start

        float t[16];
#pragma unroll
        for (int q = 0; q < 16; q++) t[q] = slotp[q*16 + lane];  // T^t: conflict-free
        float c = slotp[256 + (lane & 15)];
        float v[16];
#pragma unroll
        for (int q = 0; q < 16; q++) v[q] = __shfl_sync(0xffffffffu, s, q);
        float p0 = c, p1 = 0.f, p2 = 0.f, p3 = 0.f;
#pragma unroll
        for (int q = 0; q < 16; q += 4) {
            p0 = fmaf(t[q+0], v[q+0], p0);
            p1 = fmaf(t[q+1], v[q+1], p1);
            p2 = fmaf(t[q+2], v[q+2], p2);
            p3 = fmaf(t[q+3], v[q+3], p3);
        }
        s = (p0 + p1) + (p2 + p3);

        __syncwarp();                    // all lanes consumed slot before refill
        scan_prefetch(rbase, fb, f + DEPTH, lane);
    }
}

// ---------------------------------------------------------------------------
// Kernel 3: per (batch,frame) output: u = e - boundary correction from state,
// z = causal conv(h, u). One warp per frame, 4 outputs per lane.
// ---------------------------------------------------------------------------
__global__ void __launch_bounds__(128) k_out(const float* __restrict__ e,
                                             float* __restrict__ out)
{
    __shared__ __align__(16) float sh[4][192];   // per warp: h[80] | u[80] | s[16] a'[16]
    int w    = threadIdx.x >> 5;
    int lane = threadIdx.x & 31;
    size_t g = (size_t)blockIdx.x*4 + w;
    int b = (int)(g / F);
    int f = (int)(g - (size_t)b*F);
    float* hs = sh[w];
    float* us = hs + 80;
    float* sa = hs + 160;

    const float4* hg4 = reinterpret_cast<const float4*>(g_h + g*80);
    if (lane < 20) reinterpret_cast<float4*>(hs)[lane] = hg4[lane];
    if (lane < 16) {
        sa[lane]      = g_S [g*16 + lane];
        sa[16 + lane] = g_ap[g*16 + lane];   // a'[j+1] at index j
    }
    const float4* ef4 = reinterpret_cast<const float4*>(e + (size_t)b*L + (size_t)f*FSH);
    if (lane < 20) reinterpret_cast<float4*>(us)[lane] = ef4[lane];
    __syncwarp();

    // boundary correction: u[m] -= sum_{jj=m..15} a'[jj+1] * s[jj-m]
    if (lane < 16) {
        float corr = 0.f;
#pragma unroll
        for (int jj = 0; jj < 16; jj++)
            if (jj >= lane) corr = fmaf(sa[16+jj], sa[jj-lane], corr);
        us[lane] -= corr;
    }
    __syncwarp();

    if (lane < 20) {
        int mb = lane * 4;
        float a0 = 0.f, a1 = 0.f, a2 = 0.f, a3 = 0.f;
        for (int j = 0; j < mb; j++) {
            float uj = us[j];
            a0 = fmaf(uj, hs[mb   - j], a0);
            a1 = fmaf(uj, hs[mb+1 - j], a1);
            a2 = fmaf(uj, hs[mb+2 - j], a2);
            a3 = fmaf(uj, hs[mb+3 - j], a3);
        }
        float u0 = us[mb], u1 = us[mb+1], u2 = us[mb+2], u3 = us[mb+3];
        float h0 = hs[0], h1 = hs[1], h2 = hs[2], h3 = hs[3];
        a0 = fmaf(u0, h0, a0);
        a1 = fmaf(u0, h1, a1); a1 = fmaf(u1, h0, a1);
        a2 = fmaf(u0, h2, a2); a2 = fmaf(u1, h1, a2); a2 = fmaf(u2, h0, a2);
        a3 = fmaf(u0, h3, a3); a3 = fmaf(u1, h2, a3); a3 = fmaf(u2, h1, a3); a3 = fmaf(u3, h0, a3);
        float4 r; r.x = a0; r.y = a1; r.z = a2; r.w = a3;
        reinterpret_cast<float4*>(out + (size_t)b*L + (size_t)f*FSH)[lane] = r;
    }
}

// ---------------------------------------------------------------------------
extern "C" void kernel_launch(void* const* d_in, const int* in_sizes, int n_in,
                              void* d_out, int out_size)
{
    (void)in_sizes; (void)n_in; (void)out_size;
    const float* e   = (const float*)d_in[0];   // excit (B, L, 1)
    const float* lpc = (const float*)d_in[1];   // lpc_coef (B, F, 16)
    float* out = (float*)d_out;                 // (B, L, 1)

    k_prep<<<NT/128, 128>>>(e, lpc);
    k_scan<<<B, 32>>>();
    k_out <<<NT/4, 128>>>(e, out);
}

// round 3
// speedup vs baseline: 1.0763x; 1.0763x over previous
#include <cuda_runtime.h>
#include <cstdint>

#define B     64
#define F     3000
#define FSH   80
#define L     240000
#define EMPH  0.97f
#define NT    (B*F)
#define DEPTH 16

// Scratch (static device arrays -- allocation-free per harness rules)
__device__ __align__(16) static float g_h [(size_t)NT*80];   //  61.4 MB impulse responses
__device__ __align__(16) static float g_w [(size_t)NT*80];   //  61.4 MB zero-state responses
__device__ __align__(16) static float g_ap[(size_t)NT*16];   //  combined taps a'[1..16]
__device__ __align__(16) static float g_T [(size_t)NT*256];  // 196.6 MB transition mats (transposed)
__device__ __align__(16) static float g_S [(size_t)NT*16];   //  per-frame start states

// ---------------------------------------------------------------------------
// Kernel 1: per (batch,frame) -- combined taps a', impulse response h (ring-32,
// no spills), zero-state response w (ring-16, full 80 samples written out),
// transition matrix T (stored transposed).
// Combined filter: z[n] = e[n] - sum_{j=1..16} a'_j z[n-j],
//   a'_j = a_j - EMPH*a_{j-1}  (a_0 = 1, a_16 = 0)
// ---------------------------------------------------------------------------
__global__ void __launch_bounds__(128) k_prep(const float* __restrict__ e,
                                              const float* __restrict__ lpc)
{
    int tid = blockIdx.x*128 + threadIdx.x;
    if (tid >= NT) return;
    int b = tid / F;
    int f = tid - b*F;

    float av[16];
    const float4* a4 = reinterpret_cast<const float4*>(lpc + (size_t)tid*16);
#pragma unroll
    for (int j = 0; j < 4; j++) {
        float4 t = a4[j];
        av[4*j+0]=t.x; av[4*j+1]=t.y; av[4*j+2]=t.z; av[4*j+3]=t.w;
    }

    float ap[17];
    ap[1] = av[1] - EMPH;                 // a0 == 1 by construction
#pragma unroll
    for (int j = 2; j <= 15; j++) ap[j] = av[j] - EMPH*av[j-1];
    ap[16] = -EMPH*av[15];

    float4* apout = reinterpret_cast<float4*>(g_ap + (size_t)tid*16);
#pragma unroll
    for (int j = 0; j < 16; j += 4) {
        float4 t; t.x=ap[j+1]; t.y=ap[j+2]; t.z=ap[j+3]; t.w=ap[j+4];
        apout[j>>2] = t;
    }

    // Combined loop: impulse response h (ring of 32) and zero-state response w
    // (ring of 16), streamed to global every 4 samples. No register spills.
    const float4* ef4 = reinterpret_cast<const float4*>(e + (size_t)b*L + (size_t)f*FSH);
    float4* hout = reinterpret_cast<float4*>(g_h + (size_t)tid*80);
    float4* wout = reinterpret_cast<float4*>(g_w + (size_t)tid*80);

    float hr[32];
    float wr[16];
    float ev[4];
    float hb[4], wb[4];

#pragma unroll
    for (int m = 0; m < 80; m++) {
        if ((m & 3) == 0) {
            float4 t = ef4[m>>2];
            ev[0]=t.x; ev[1]=t.y; ev[2]=t.z; ev[3]=t.w;
        }
        // h recursion
        float acch;
        if (m == 0) acch = 1.f;
        else {
            acch = 0.f;
#pragma unroll
            for (int j = 1; j <= 16; j++)
                if (j <= m) acch = fmaf(ap[j], hr[(m-j) & 31], acch);
            acch = -acch;
        }
        hr[m & 31] = acch;
        // w recursion (zero-state response to this frame's excitation)
        float accw = ev[m & 3];
#pragma unroll
        for (int j = 1; j <= 16; j++)
            if (j <= m) accw = fmaf(-ap[j], wr[(m-j) & 15], accw);
        wr[m & 15] = accw;

        hb[m & 3] = acch;
        wb[m & 3] = accw;
        if ((m & 3) == 3) {
            float4 t;
            t.x=hb[0]; t.y=hb[1]; t.z=hb[2]; t.w=hb[3]; hout[m>>2] = t;
            t.x=wb[0]; t.y=wb[1]; t.z=wb[2]; t.w=wb[3]; wout[m>>2] = t;
        }
    }

    // T[i][q] = -sum_{mm=0..15-q} h[79-i-mm] * a'[mm+q+1]
    // needs h[49..79] only -> lives in the ring ((49..79)&31 misses slot 16).
    // stored transposed: g_T[q*16+i] so scan reads are conflict-free
    float4* Tout = reinterpret_cast<float4*>(g_T + (size_t)tid*256);
#pragma unroll
    for (int q = 0; q < 16; q++) {
#pragma unroll
        for (int i4 = 0; i4 < 16; i4 += 4) {
            float v[4];
#pragma unroll
            for (int k = 0; k < 4; k++) {
                int i = i4 + k;
                float acc = 0.f;
#pragma unroll
                for (int mm = 0; mm <= 15-q; mm++)
                    acc = fmaf(hr[(79-i-mm) & 31], ap[mm+q+1], acc);
                v[k] = -acc;
            }
            float4 t; t.x=v[0]; t.y=v[1]; t.z=v[2]; t.w=v[3];
            Tout[(q*16+i4)>>2] = t;
        }
    }
}

// ---------------------------------------------------------------------------
// Kernel 2: sequential state scan per batch: s_{f+1} = T_f s_f + c_f,
// c_i = w_f[79-i]. One warp per batch; lane i owns row i; state broadcast via
// shfl. T/w-tail streamed through a DEPTH-deep cp.async ring.
// ---------------------------------------------------------------------------
__device__ __forceinline__ void scan_prefetch(uint32_t rbase, size_t fb, int f, int lane)
{
    if (f < F) {
        uint32_t slot = rbase + (uint32_t)(f & (DEPTH-1)) * 272u * 4u;
        const float* Tf = g_T + (fb + (size_t)f)*256;
        const float* Wf = g_w + (fb + (size_t)f)*80 + 64;   // w[64..79]
        asm volatile("cp.async.ca.shared.global [%0], [%1], 16;"
                     :: "r"(slot + (uint32_t)lane*16u), "l"(Tf + lane*4) : "memory");
        asm volatile("cp.async.ca.shared.global [%0], [%1], 16;"
                     :: "r"(slot + (uint32_t)(lane+32)*16u), "l"(Tf + (lane+32)*4) : "memory");
        if (lane < 4)
            asm volatile("cp.async.ca.shared.global [%0], [%1], 16;"
                         :: "r"(slot + 1024u + (uint32_t)lane*16u), "l"(Wf + lane*4) : "memory");
    }
    asm volatile("cp.async.commit_group;" ::: "memory");
}

__global__ void __launch_bounds__(32) k_scan()
{
    __shared__ __align__(16) float ring[DEPTH][272];
    int b = blockIdx.x;
    int lane = threadIdx.x;
    size_t fb = (size_t)b * F;
    uint32_t rbase = (uint32_t)__cvta_generic_to_shared(&ring[0][0]);

#pragma unroll 1
    for (int f = 0; f < DEPTH; f++) scan_prefetch(rbase, fb, f, lane);

    float s = 0.f;                       // lane i (<16) holds state s_i
    float* Sout = g_S + fb*16;

#pragma unroll 1
    for (int f = 0; f < F; f++) {
        asm volatile("cp.async.wait_group 15;" ::: "memory");
        __syncwarp();
        const float* slotp = &ring[f & (DEPTH-1)][0];

        if (lane < 16) Sout[(size_t)f*16 + lane] = s;   // state at frame start

        float t[16];
#pragma unroll
        for (int q = 0; q < 16; q++) t[q] = slotp[q*16 + lane];  // T^t: conflict-free
        float c = slotp[256 + 15 - (lane & 15)];                 // c_i = w[79-i]
        float v[16];
#pragma unroll
        for (int q = 0; q < 16; q++) v[q] = __shfl_sync(0xffffffffu, s, q);
        float p0 = c, p1 = 0.f, p2 = 0.f, p3 = 0.f;
#pragma unroll
        for (int q = 0; q < 16; q += 4) {
            p0 = fmaf(t[q+0], v[q+0], p0);
            p1 = fmaf(t[q+1], v[q+1], p1);
            p2 = fmaf(t[q+2], v[q+2], p2);
            p3 = fmaf(t[q+3], v[q+3], p3);
        }
        s = (p0 + p1) + (p2 + p3);

        __syncwarp();                    // all lanes consumed slot before refill
        scan_prefetch(rbase, fb, f + DEPTH, lane);
    }
}

// ---------------------------------------------------------------------------
// Kernel 3: per frame output: z[m] = w[m] + sum_{k=0..15} d[k] * h[m-k],
// d[k] = -sum_{jj=k..15} a'[jj+1] * s[jj-k]  (boundary-correction impulse).
// One warp per frame; lane l produces outputs l, l+32, and (l<16) l+64.
// h buffer padded both sides with zeros so the unpredicated FMA indexing
// hs[lane + 64 - k + 16] (max 111) is always in-bounds.
// ---------------------------------------------------------------------------
__global__ void __launch_bounds__(256) k_out(float* __restrict__ out)
{
    __shared__ __align__(16) float hp[8][112];  // [0..15]=0, [16..95]=h, [96..111]=0
    int w    = threadIdx.x >> 5;
    int lane = threadIdx.x & 31;
    size_t g = (size_t)blockIdx.x*8 + w;
    size_t base = g * 80;                        // frame offset in samples
    float* hs = hp[w];

    // load h with 16-zero pad on both sides (28 float4 slots total)
    if (lane < 4 || (lane >= 24 && lane < 28)) {
        float4 z; z.x=z.y=z.z=z.w=0.f;
        reinterpret_cast<float4*>(hs)[lane] = z;
    } else if (lane < 24) {
        reinterpret_cast<float4*>(hs)[lane] =
            reinterpret_cast<const float4*>(g_h + base)[lane - 4];
    }

    // per-lane registers: s, ap (lanes 0..15)
    float sreg  = (lane < 16) ? g_S [g*16 + lane] : 0.f;
    float apreg = (lane < 16) ? g_ap[g*16 + lane] : 0.f;   // a'[lane+1]

    // w (ZSR) loads, coalesced
    float acc0 = g_w[base + lane];
    float acc1 = g_w[base + 32 + lane];
    float acc2 = (lane < 16) ? g_w[base + 64 + lane] : 0.f;

    // d[k] on lane k: d = -sum_{t=0..15-k} a'[k+t+1] * s[t]
    float d = 0.f;
#pragma unroll
    for (int t = 0; t < 16; t++) {
        float apv = __shfl_sync(0xffffffffu, apreg, (lane + t) & 31);
        float sv  = __shfl_sync(0xffffffffu, sreg, t);
        if (t <= 15 - lane) d = fmaf(apv, sv, d);
    }
    d = -d;

    __syncwarp();

#pragma unroll
    for (int k = 0; k < 16; k++) {
        float dk = __shfl_sync(0xffffffffu, d, k);
        acc0 = fmaf(dk, hs[lane      - k + 16], acc0);
        acc1 = fmaf(dk, hs[lane + 32 - k + 16], acc1);
        acc2 = fmaf(dk, hs[lane + 64 - k + 16], acc2);  // lane>=16 reads the zero pad
    }

    out[base + lane]      = acc0;
    out[base + 32 + lane] = acc1;
    if (lane < 16) out[base + 64 + lane] = acc2;
}

// ---------------------------------------------------------------------------
extern "C" void kernel_launch(void* const* d_in, const int* in_sizes, int n_in,
                              void* d_out, int out_size)
{
    (void)in_sizes; (void)n_in; (void)out_size;
    const float* e   = (const float*)d_in[0];   // excit (B, L, 1)
    const float* lpc = (const float*)d_in[1];   // lpc_coef (B, F, 16)
    float* out = (float*)d_out;                 // (B, L, 1)

    k_prep<<<NT/128, 128>>>(e, lpc);
    k_scan<<<B, 32>>>();
    k_out <<<NT/8, 256>>>(out);
}

// round 4
// speedup vs baseline: 1.4964x; 1.3902x over previous
#include <cuda_runtime.h>
#include <cstdint>

#define B     64
#define F     3000
#define FSH   80
#define L     240000
#define EMPH  0.97f
#define NT    (B*F)
#define G     60          // frames per scan group
#define NG    50          // groups per batch (G*NG == F)
#define DEPTH_G 4
#define DEPTH_F 8

// Scratch (static device arrays -- allocation-free per harness rules)
__device__ __align__(16) static float g_h [(size_t)NT*80];   // impulse responses
__device__ __align__(16) static float g_w [(size_t)NT*80];   // zero-state responses
__device__ __align__(16) static float g_ap[(size_t)NT*16];   // combined taps a'[1..16]
__device__ __align__(16) static float g_T [(size_t)NT*256];  // transition mats (transposed)
__device__ __align__(16) static float g_S [(size_t)NT*16];   // per-frame start states
__device__ __align__(16) static float g_M [(size_t)B*NG*256];// group composite matrices
__device__ __align__(16) static float g_Cg[(size_t)B*NG*16]; // group composite offsets
__device__ __align__(16) static float g_Sg[(size_t)B*NG*16]; // group start states

// ---------------------------------------------------------------------------
// Kernel 1: per (batch,frame) -- combined taps, impulse response h (ring-32),
// zero-state response w (ring-16), transition matrix T (transposed).
// Critical-path fix: x[m] = fmaf(an[1], x[m-1], part) with part accumulated
// off-chain (an = -a'), so the recursion chain is 1 FMA (4cyc) per sample.
// ---------------------------------------------------------------------------
__global__ void __launch_bounds__(128) k_prep(const float* __restrict__ e,
                                              const float* __restrict__ lpc)
{
    int tid = blockIdx.x*128 + threadIdx.x;
    if (tid >= NT) return;
    int b = tid / F;
    int f = tid - b*F;

    float av[16];
    const float4* a4 = reinterpret_cast<const float4*>(lpc + (size_t)tid*16);
#pragma unroll
    for (int j = 0; j < 4; j++) {
        float4 t = a4[j];
        av[4*j+0]=t.x; av[4*j+1]=t.y; av[4*j+2]=t.z; av[4*j+3]=t.w;
    }

    // an[j] = -a'[j],  a'_j = a_j - EMPH*a_{j-1}  (a_0 = 1, a_16 = 0)
    float an[17];
    an[1] = EMPH - av[1];
#pragma unroll
    for (int j = 2; j <= 15; j++) an[j] = EMPH*av[j-1] - av[j];
    an[16] = EMPH*av[15];

    float4* apout = reinterpret_cast<float4*>(g_ap + (size_t)tid*16);
#pragma unroll
    for (int j = 0; j < 16; j += 4) {
        float4 t; t.x=-an[j+1]; t.y=-an[j+2]; t.z=-an[j+3]; t.w=-an[j+4];
        apout[j>>2] = t;
    }

    const float4* ef4 = reinterpret_cast<const float4*>(e + (size_t)b*L + (size_t)f*FSH);
    float4* hout = reinterpret_cast<float4*>(g_h + (size_t)tid*80);
    float4* wout = reinterpret_cast<float4*>(g_w + (size_t)tid*80);

    float hr[32];
    float wr[16];
    float ev[4];
    float hb[4], wb[4];

#pragma unroll
    for (int m = 0; m < 80; m++) {
        if ((m & 3) == 0) {
            float4 t = ef4[m>>2];
            ev[0]=t.x; ev[1]=t.y; ev[2]=t.z; ev[3]=t.w;
        }
        // h recursion: short chain
        float acch;
        if (m == 0) acch = 1.f;
        else {
            float part = 0.f;
#pragma unroll
            for (int j = 2; j <= 16; j++)
                if (j <= m) part = fmaf(an[j], hr[(m-j) & 31], part);
            acch = fmaf(an[1], hr[(m-1) & 31], part);
        }
        hr[m & 31] = acch;
        // w recursion (zero-state response): short chain
        float partw = ev[m & 3];
#pragma unroll
        for (int j = 2; j <= 16; j++)
            if (j <= m) partw = fmaf(an[j], wr[(m-j) & 15], partw);
        float accw = (m >= 1) ? fmaf(an[1], wr[(m-1) & 15], partw) : partw;
        wr[m & 15] = accw;

        hb[m & 3] = acch;
        wb[m & 3] = accw;
        if ((m & 3) == 3) {
            float4 t;
            t.x=hb[0]; t.y=hb[1]; t.z=hb[2]; t.w=hb[3]; hout[m>>2] = t;
            t.x=wb[0]; t.y=wb[1]; t.z=wb[2]; t.w=wb[3]; wout[m>>2] = t;
        }
    }

    // T[i][q] = sum_{mm=0..15-q} h[79-i-mm] * an[mm+q+1]
    // stored transposed: g_T[q*16+i]
    float4* Tout = reinterpret_cast<float4*>(g_T + (size_t)tid*256);
#pragma unroll
    for (int q = 0; q < 16; q++) {
#pragma unroll
        for (int i4 = 0; i4 < 16; i4 += 4) {
            float v[4];
#pragma unroll
            for (int k = 0; k < 4; k++) {
                int i = i4 + k;
                float acc = 0.f;
#pragma unroll
                for (int mm = 0; mm <= 15-q; mm++)
                    acc = fmaf(hr[(79-i-mm) & 31], an[mm+q+1], acc);
                v[k] = acc;
            }
            float4 t; t.x=v[0]; t.y=v[1]; t.z=v[2]; t.w=v[3];
            Tout[(q*16+i4)>>2] = t;
        }
    }
}

// ---------------------------------------------------------------------------
// cp.async prefetch of one frame's T (256 floats) + w tail (16 floats) into a
// ring slot. 'valid' guards OOB; commit always (keeps wait counts aligned).
// ---------------------------------------------------------------------------
__device__ __forceinline__ void frame_prefetch(uint32_t slot, size_t fg, int lane, bool valid)
{
    if (valid) {
        const float* Tf = g_T + fg*256;
        const float* Wf = g_w + fg*80 + 64;   // w[64..79]
        asm volatile("cp.async.ca.shared.global [%0], [%1], 16;"
                     :: "r"(slot + (uint32_t)lane*16u), "l"(Tf + lane*4) : "memory");
        asm volatile("cp.async.ca.shared.global [%0], [%1], 16;"
                     :: "r"(slot + (uint32_t)(lane+32)*16u), "l"(Tf + (lane+32)*4) : "memory");
        if (lane < 4)
            asm volatile("cp.async.ca.shared.global [%0], [%1], 16;"
                         :: "r"(slot + 1024u + (uint32_t)lane*16u), "l"(Wf + lane*4) : "memory");
    }
    asm volatile("cp.async.commit_group;" ::: "memory");
}

// ---------------------------------------------------------------------------
// Kernel 2: group composites. One warp per (batch,group): M <- T_f * M,
// c <- T_f * c + c_f over the group's G frames. M kept in shared (row-major,
// row stride 20, c at column 16). Lane = (row i = lane&15, half h = lane>>4).
// ---------------------------------------------------------------------------
__global__ void __launch_bounds__(128) k_gscan()
{
    __shared__ __align__(16) float ring[4][DEPTH_G][272];
    __shared__ __align__(16) float Mb[4][16*20];
    int w    = threadIdx.x >> 5;
    int lane = threadIdx.x & 31;
    size_t gg = (size_t)blockIdx.x*4 + w;
    int b = (int)(gg / NG), g = (int)(gg - (size_t)b*NG);
    size_t f0 = (size_t)b*F + (size_t)g*G;
    int i = lane & 15, h = lane >> 4;
    float* M = Mb[w];
    uint32_t rbase = (uint32_t)__cvta_generic_to_shared(&ring[w][0][0]);

    // M = I, c = 0
#pragma unroll
    for (int j = 0; j < 8; j++) M[i*20 + 8*h + j] = ((8*h + j) == i) ? 1.f : 0.f;
    if (h == 0) M[i*20 + 16] = 0.f;

#pragma unroll
    for (int k = 0; k < DEPTH_G; k++)
        frame_prefetch(rbase + (uint32_t)k*272u*4u, f0 + k, lane, k < G);
    __syncwarp();

#pragma unroll 1
    for (int k = 0; k < G; k++) {
        asm volatile("cp.async.wait_group %0;" :: "n"(DEPTH_G-1) : "memory");
        __syncwarp();
        const float* slot = &ring[w][k & (DEPTH_G-1)][0];

        float mp[8];
#pragma unroll
        for (int j = 0; j < 8; j++) mp[j] = 0.f;
        float cacc = slot[256 + 15 - i];          // c_f[i] = w_f[79-i]
#pragma unroll
        for (int q = 0; q < 16; q++) {
            float tq = slot[q*16 + i];            // T[i][q]
            const float4* mq = reinterpret_cast<const float4*>(M + q*20 + 8*h);
            float4 m0 = mq[0], m1 = mq[1];
            mp[0]=fmaf(tq,m0.x,mp[0]); mp[1]=fmaf(tq,m0.y,mp[1]);
            mp[2]=fmaf(tq,m0.z,mp[2]); mp[3]=fmaf(tq,m0.w,mp[3]);
            mp[4]=fmaf(tq,m1.x,mp[4]); mp[5]=fmaf(tq,m1.y,mp[5]);
            mp[6]=fmaf(tq,m1.z,mp[6]); mp[7]=fmaf(tq,m1.w,mp[7]);
            cacc = fmaf(tq, M[q*20 + 16], cacc);  // same on both halves; h=0 stores
        }
        __syncwarp();
        float4 s0, s1;
        s0.x=mp[0]; s0.y=mp[1]; s0.z=mp[2]; s0.w=mp[3];
        s1.x=mp[4]; s1.y=mp[5]; s1.z=mp[6]; s1.w=mp[7];
        float4* mo = reinterpret_cast<float4*>(M + i*20 + 8*h);
        mo[0] = s0; mo[1] = s1;
        if (h == 0) M[i*20 + 16] = cacc;
        __syncwarp();

        frame_prefetch(rbase + (uint32_t)((k+DEPTH_G) & (DEPTH_G-1))*272u*4u,
                       f0 + k + DEPTH_G, lane, (k + DEPTH_G) < G);
    }

    // write M_g (row-major [i][e]) and c_g
    float4* Mo = reinterpret_cast<float4*>(g_M + gg*256 + (size_t)i*16 + 8*h);
    Mo[0] = reinterpret_cast<float4*>(M + i*20 + 8*h)[0];
    Mo[1] = reinterpret_cast<float4*>(M + i*20 + 8*h)[1];
    if (h == 0) g_Cg[gg*16 + i] = M[i*20 + 16];
}

// ---------------------------------------------------------------------------
// Kernel 3: serial scan over NG group composites per batch (tiny).
// s_{g+1} = M_g s_g + c_g; writes group start states.
// ---------------------------------------------------------------------------
__global__ void __launch_bounds__(32) k_mscan()
{
    int b = blockIdx.x;
    int lane = threadIdx.x;
    int i = lane & 15;
    float s = 0.f;

#pragma unroll 1
    for (int g = 0; g < NG; g++) {
        size_t gg = (size_t)b*NG + g;
        if (lane < 16) g_Sg[gg*16 + lane] = s;
        float t[16];
        const float4* Mr = reinterpret_cast<const float4*>(g_M + gg*256 + (size_t)i*16);
#pragma unroll
        for (int q4 = 0; q4 < 4; q4++) {
            float4 tt = Mr[q4];
            t[4*q4+0]=tt.x; t[4*q4+1]=tt.y; t[4*q4+2]=tt.z; t[4*q4+3]=tt.w;
        }
        float c = g_Cg[gg*16 + i];
        float v[16];
#pragma unroll
        for (int q = 0; q < 16; q++) v[q] = __shfl_sync(0xffffffffu, s, q);
        float p0 = c, p1 = 0.f, p2 = 0.f, p3 = 0.f;
#pragma unroll
        for (int q = 0; q < 16; q += 4) {
            p0 = fmaf(t[q+0], v[q+0], p0);
            p1 = fmaf(t[q+1], v[q+1], p1);
            p2 = fmaf(t[q+2], v[q+2], p2);
            p3 = fmaf(t[q+3], v[q+3], p3);
        }
        s = (p0 + p1) + (p2 + p3);
    }
}

// ---------------------------------------------------------------------------
// Kernel 4: within-group re-scan (parallel over groups): s_{f+1} = T_f s_f + c_f
// starting from the group start state; writes per-frame start states g_S.
// ---------------------------------------------------------------------------
__global__ void __launch_bounds__(128) k_fscan()
{
    __shared__ __align__(16) float ring[4][DEPTH_F][272];
    int w    = threadIdx.x >> 5;
    int lane = threadIdx.x & 31;
    size_t gg = (size_t)blockIdx.x*4 + w;
    int b = (int)(gg / NG), g = (int)(gg - (size_t)b*NG);
    size_t f0 = (size_t)b*F + (size_t)g*G;
    uint32_t rbase = (uint32_t)__cvta_generic_to_shared(&ring[w][0][0]);

#pragma unroll
    for (int k = 0; k < DEPTH_F; k++)
        frame_prefetch(rbase + (uint32_t)k*272u*4u, f0 + k, lane, k < G);

    float s = (lane < 16) ? g_Sg[gg*16 + lane] : 0.f;
    float* Sout = g_S + f0*16;

#pragma unroll 1
    for (int k = 0; k < G; k++) {
        asm volatile("cp.async.wait_group %0;" :: "n"(DEPTH_F-1) : "memory");
        __syncwarp();
        const float* slot = &ring[w][k & (DEPTH_F-1)][0];

        if (lane < 16) Sout[(size_t)k*16 + lane] = s;

        float t[16];
#pragma unroll
        for (int q = 0; q < 16; q++) t[q] = slot[q*16 + lane];
        float c = slot[256 + 15 - (lane & 15)];
        float v[16];
#pragma unroll
        for (int q = 0; q < 16; q++) v[q] = __shfl_sync(0xffffffffu, s, q);
        float p0 = c, p1 = 0.f, p2 = 0.f, p3 = 0.f;
#pragma unroll
        for (int q = 0; q < 16; q += 4) {
            p0 = fmaf(t[q+0], v[q+0], p0);
            p1 = fmaf(t[q+1], v[q+1], p1);
            p2 = fmaf(t[q+2], v[q+2], p2);
            p3 = fmaf(t[q+3], v[q+3], p3);
        }
        s = (p0 + p1) + (p2 + p3);

        __syncwarp();
        frame_prefetch(rbase + (uint32_t)((k+DEPTH_F) & (DEPTH_F-1))*272u*4u,
                       f0 + k + DEPTH_F, lane, (k + DEPTH_F) < G);
    }
}

// ---------------------------------------------------------------------------
// Kernel 5: per frame output: z[m] = w[m] + sum_{k=0..15} d[k] * h[m-k],
// d[k] = -sum_{jj=k..15} a'[jj+1] * s[jj-k].
// ---------------------------------------------------------------------------
__global__ void __launch_bounds__(256) k_out(float* __restrict__ out)
{
    __shared__ __align__(16) float hp[8][112];  // [0..15]=0, [16..95]=h, [96..111]=0
    int w    = threadIdx.x >> 5;
    int lane = threadIdx.x & 31;
    size_t g = (size_t)blockIdx.x*8 + w;
    size_t base = g * 80;
    float* hs = hp[w];

    if (lane < 4 || (lane >= 24 && lane < 28)) {
        float4 z; z.x=z.y=z.z=z.w=0.f;
        reinterpret_cast<float4*>(hs)[lane] = z;
    } else if (lane < 24) {
        reinterpret_cast<float4*>(hs)[lane] =
            reinterpret_cast<const float4*>(g_h + base)[lane - 4];
    }

    float sreg  = (lane < 16) ? g_S [g*16 + lane] : 0.f;
    float apreg = (lane < 16) ? g_ap[g*16 + lane] : 0.f;   // a'[lane+1]

    float acc0 = g_w[base + lane];
    float acc1 = g_w[base + 32 + lane];
    float acc2 = (lane < 16) ? g_w[base + 64 + lane] : 0.f;

    float d = 0.f;
#pragma unroll
    for (int t = 0; t < 16; t++) {
        float apv = __shfl_sync(0xffffffffu, apreg, (lane + t) & 31);
        float sv  = __shfl_sync(0xffffffffu, sreg, t);
        if (t <= 15 - lane) d = fmaf(apv, sv, d);
    }
    d = -d;

    __syncwarp();

#pragma unroll
    for (int k = 0; k < 16; k++) {
        float dk = __shfl_sync(0xffffffffu, d, k);
        acc0 = fmaf(dk, hs[lane      - k + 16], acc0);
        acc1 = fmaf(dk, hs[lane + 32 - k + 16], acc1);
        acc2 = fmaf(dk, hs[lane + 64 - k + 16], acc2);
    }

    out[base + lane]      = acc0;
    out[base + 32 + lane] = acc1;
    if (lane < 16) out[base + 64 + lane] = acc2;
}

// ---------------------------------------------------------------------------
extern "C" void kernel_launch(void* const* d_in, const int* in_sizes, int n_in,
                              void* d_out, int out_size)
{
    (void)in_sizes; (void)n_in; (void)out_size;
    const float* e   = (const float*)d_in[0];   // excit (B, L, 1)
    const float* lpc = (const float*)d_in[1];   // lpc_coef (B, F, 16)
    float* out = (float*)d_out;                 // (B, L, 1)

    k_prep <<<NT/128, 128>>>(e, lpc);
    k_gscan<<<(B*NG)/4, 128>>>();
    k_mscan<<<B, 32>>>();
    k_fscan<<<(B*NG)/4, 128>>>();
    k_out  <<<NT/8, 256>>>(out);
}

// round 5
// speedup vs baseline: 3.7478x; 2.5046x over previous
#include <cuda_runtime.h>
#include <cstdint>

#define B     64
#define F     3000
#define FSH   80
#define L     240000
#define EMPH  0.97f
#define NT    (B*F)
#define G     50          // frames emitted per group
#define NGRP  (F/G)       // 60 groups per batch
#define WARM  12          // warm-up frames (state contraction ~0.2^12)
#define DEPTH 4           // cp.async ring depth
#define SLOT  208         // floats per ring slot: 16 zero | 80 h | 16 zero | 80 w | 16 an

// Scratch (static device arrays -- allocation-free per harness rules)
__device__ __align__(16) static float g_h [(size_t)NT*80];   // impulse responses
__device__ __align__(16) static float g_w [(size_t)NT*80];   // zero-state responses
__device__ __align__(16) static float g_an[(size_t)NT*16];   // an[j] = -a'[j+1], j=0..15

// ---------------------------------------------------------------------------
// Kernel 1: per (batch,frame) thread -- negated combined taps an, impulse
// response h of 1/A'(z) (ring-32), zero-state response w (ring-16).
// Combined filter: z[n] = e[n] + sum_j an[j] z[n-j],  an = -(a - EMPH*a_<<1).
// Chain kept short: x[m] = fmaf(an1, x[m-1], part) with part off-chain.
// Steady-state loop body is 32 samples (= ring period) so all ring indices
// are static across both loop trips -> no spills, modest code size.
// ---------------------------------------------------------------------------
__global__ void __launch_bounds__(128) k_prep(const float* __restrict__ e,
                                              const float* __restrict__ lpc)
{
    int tid = blockIdx.x*128 + threadIdx.x;
    if (tid >= NT) return;
    int b = tid / F;
    int f = tid - b*F;

    float av[16];
    const float4* a4 = reinterpret_cast<const float4*>(lpc + (size_t)tid*16);
#pragma unroll
    for (int j = 0; j < 4; j++) {
        float4 t = a4[j];
        av[4*j+0]=t.x; av[4*j+1]=t.y; av[4*j+2]=t.z; av[4*j+3]=t.w;
    }

    // an[j] = -a'[j],  a'_j = a_j - EMPH*a_{j-1}  (a_0 = 1, a_16 = 0)
    float an[17];
    an[1] = EMPH - av[1];
#pragma unroll
    for (int j = 2; j <= 15; j++) an[j] = EMPH*av[j-1] - av[j];
    an[16] = EMPH*av[15];

    float4* anout = reinterpret_cast<float4*>(g_an + (size_t)tid*16);
#pragma unroll
    for (int j = 0; j < 16; j += 4) {
        float4 t; t.x=an[j+1]; t.y=an[j+2]; t.z=an[j+3]; t.w=an[j+4];
        anout[j>>2] = t;
    }

    const float4* ef4 = reinterpret_cast<const float4*>(e + (size_t)b*L + (size_t)f*FSH);
    float4* hout = reinterpret_cast<float4*>(g_h + (size_t)tid*80);
    float4* wout = reinterpret_cast<float4*>(g_w + (size_t)tid*80);

    float hr[32];
    float wr[16];
    float hb[4], wb[4];

    // --- startup: m = 0..15 (triangular tap counts), fully unrolled ---
#pragma unroll
    for (int m = 0; m < 16; m++) {
        float4 t;
        float evm;
        {   // scalar load of e[m] (grouped float4 every 4)
            if ((m & 3) == 0) { t = ef4[m>>2]; }
            evm = (m & 3) == 0 ? t.x : 0.f; // placeholder; replaced below
        }
        // simpler: direct scalar loads for startup (only 16 of them)
        evm = reinterpret_cast<const float*>(ef4)[m];

        float acch;
        if (m == 0) acch = 1.f;
        else {
            float part = 0.f;
#pragma unroll
            for (int j = 2; j <= m; j++) part = fmaf(an[j], hr[m-j], part);
            acch = fmaf(an[1], hr[m-1], part);
        }
        hr[m] = acch;

        float partw = evm;
#pragma unroll
        for (int j = 2; j <= m; j++) partw = fmaf(an[j], wr[m-j], partw);
        float accw = (m >= 1) ? fmaf(an[1], wr[m-1], partw) : partw;
        wr[m] = accw;

        hb[m & 3] = acch;
        wb[m & 3] = accw;
        if ((m & 3) == 3) {
            float4 o;
            o.x=hb[0]; o.y=hb[1]; o.z=hb[2]; o.w=hb[3]; hout[m>>2] = o;
            o.x=wb[0]; o.y=wb[1]; o.z=wb[2]; o.w=wb[3]; wout[m>>2] = o;
        }
    }

    // --- steady state: m = 16..79 in two trips of the 32-sample body.
    // (base+u-j) & 31 is identical for base=16 and base=48, so indices stay
    // static and the ring arrays never spill.
#pragma unroll 1
    for (int base = 16; base < 80; base += 32) {
#pragma unroll
        for (int u = 0; u < 32; u += 4) {
            float4 ev = ef4[(base + u) >> 2];
            float evl[4] = {ev.x, ev.y, ev.z, ev.w};
#pragma unroll
            for (int k = 0; k < 4; k++) {
                int m = base + u + k;     // known modulo 32 at compile time
                float part = 0.f;
#pragma unroll
                for (int j = 2; j <= 16; j++)
                    part = fmaf(an[j], hr[(m-j) & 31], part);
                float acch = fmaf(an[1], hr[(m-1) & 31], part);
                hr[m & 31] = acch;

                float partw = evl[k];
#pragma unroll
                for (int j = 2; j <= 16; j++)
                    partw = fmaf(an[j], wr[(m-j) & 15], partw);
                float accw = fmaf(an[1], wr[(m-1) & 15], partw);
                wr[m & 15] = accw;

                hb[k] = acch;
                wb[k] = accw;
            }
            float4 o;
            o.x=hb[0]; o.y=hb[1]; o.z=hb[2]; o.w=hb[3]; hout[(base+u)>>2] = o;
            o.x=wb[0]; o.y=wb[1]; o.z=wb[2]; o.w=wb[3]; wout[(base+u)>>2] = o;
        }
    }
}

// ---------------------------------------------------------------------------
// prefetch one frame's (h, w, an) into a ring slot via cp.async.
// slot layout (floats): [0..16)=0 | [16..96)=h | [96..112)=0 | [112..192)=w
//                       | [192..208)=an.  Zero pads are written once.
// ---------------------------------------------------------------------------
__device__ __forceinline__ void fused_prefetch(uint32_t slot, size_t fg, int lane, bool valid)
{
    if (valid) {
        if (lane < 20) {
            asm volatile("cp.async.ca.shared.global [%0], [%1], 16;"
                         :: "r"(slot + 64u  + (uint32_t)lane*16u),
                            "l"(g_h + fg*80 + lane*4) : "memory");
            asm volatile("cp.async.ca.shared.global [%0], [%1], 16;"
                         :: "r"(slot + 448u + (uint32_t)lane*16u),
                            "l"(g_w + fg*80 + lane*4) : "memory");
        }
        if (lane < 4)
            asm volatile("cp.async.ca.shared.global [%0], [%1], 16;"
                         :: "r"(slot + 768u + (uint32_t)lane*16u),
                            "l"(g_an + fg*16 + lane*4) : "memory");
    }
    asm volatile("cp.async.commit_group;" ::: "memory");
}

// ---------------------------------------------------------------------------
// Kernel 2: fused scan + output. One warp per (batch, group of G frames).
// Runs WARM warm-up frames (zero initial state; contraction ~0.2^WARM makes
// the state error < 1e-8; group 0 starts at frame 0 exactly), then emits
// G frames. Per frame:
//   r[k]   = sum_{t<=15-k} an[k+t+1] * s[t]      (lane k, shfl broadcast of s)
//   z[m]   = w[m] + sum_{k<16} r[k] * h[m-k]     (lane l -> m = l, l+32, l+64)
//   s'_i   = z[79-i]                             (shfl of the top outputs)
// ---------------------------------------------------------------------------
__global__ void __launch_bounds__(256) k_fused(float* __restrict__ out)
{
    __shared__ __align__(16) float ring[8][DEPTH][SLOT];
    int w    = threadIdx.x >> 5;
    int lane = threadIdx.x & 31;
    size_t gg = (size_t)blockIdx.x*8 + w;
    int b = (int)(gg / NGRP), grp = (int)(gg - (size_t)b*NGRP);
    int f0 = grp * G;
    int fstart = (f0 >= WARM) ? f0 - WARM : 0;
    int nfr = f0 + G - fstart;
    size_t fgbase = (size_t)b*F + fstart;
    uint32_t rbase = (uint32_t)__cvta_generic_to_shared(&ring[w][0][0]);

    // zero the pads once (cp.async never touches them)
    if (lane < 16) {
#pragma unroll
        for (int k = 0; k < DEPTH; k++) {
            ring[w][k][lane]      = 0.f;
            ring[w][k][96 + lane] = 0.f;
        }
    }
    __syncwarp();

#pragma unroll
    for (int k = 0; k < DEPTH; k++)
        fused_prefetch(rbase + (uint32_t)k*SLOT*4u, fgbase + k, lane, k < nfr);

    float s = 0.f;                       // lane i<16 holds s_i = z_prev[79-i]
    float* outb = out + ((size_t)b*L + (size_t)fstart*FSH);

#pragma unroll 1
    for (int j = 0; j < nfr; j++) {
        asm volatile("cp.async.wait_group %0;" :: "n"(DEPTH-1) : "memory");
        __syncwarp();
        const float* slot = &ring[w][j & (DEPTH-1)][0];
        const float* h_s  = slot;          // index m+16 gives h[m], pads zero
        const float* w_s  = slot + 112;
        const float* an_s = slot + 192;    // an_s[j] = -a'[j+1]

        // r on lane k (k<16): r = sum_t an'[k+t] * s[t]
        float r = 0.f;
#pragma unroll
        for (int t = 0; t < 16; t++) {
            float sv = __shfl_sync(0xffffffffu, s, t);
            if (t <= 15 - lane) r = fmaf(an_s[lane + t], sv, r);
        }

        // conv: z[m] = w[m] + sum_k r[k] h[m-k]
        float acc0 = w_s[lane];
        float acc1 = w_s[lane + 32];
        float acc2 = (lane < 16) ? w_s[lane + 64] : 0.f;
#pragma unroll
        for (int k = 0; k < 16; k++) {
            float rk = __shfl_sync(0xffffffffu, r, k);
            acc0 = fmaf(rk, h_s[lane      - k + 16], acc0);
            acc1 = fmaf(rk, h_s[lane + 32 - k + 16], acc1);
            acc2 = fmaf(rk, h_s[lane + 64 - k + 16], acc2);  // pads keep it in-bounds
        }

        if (j >= f0 - fstart) {          // emit only the group's own frames
            float* ob = outb + (size_t)j*FSH;
            ob[lane]      = acc0;
            ob[lane + 32] = acc1;
            if (lane < 16) ob[lane + 64] = acc2;
        }

        // next state: s_i = z[79-i] = acc2 of lane (15-i)
        float ns = __shfl_sync(0xffffffffu, acc2, (15 - lane) & 31);
        s = (lane < 16) ? ns : 0.f;

        __syncwarp();                    // all lanes done reading the slot
        fused_prefetch(rbase + (uint32_t)(j & (DEPTH-1))*SLOT*4u,
                       fgbase + j + DEPTH, lane, (j + DEPTH) < nfr);
    }
}

// ---------------------------------------------------------------------------
extern "C" void kernel_launch(void* const* d_in, const int* in_sizes, int n_in,
                              void* d_out, int out_size)
{
    (void)in_sizes; (void)n_in; (void)out_size;
    const float* e   = (const float*)d_in[0];   // excit (B, L, 1)
    const float* lpc = (const float*)d_in[1];   // lpc_coef (B, F, 16)
    float* out = (float*)d_out;                 // (B, L, 1)

    k_prep <<<NT/128, 128>>>(e, lpc);
    k_fused<<<(B*NGRP)/8, 256>>>(out);
}

// round 6
// speedup vs baseline: 4.9690x; 1.3258x over previous
#include <cuda_runtime.h>
#include <cstdint>

#define B     64
#define F     3000
#define FSH   80
#define L     240000
#define EMPH  0.97f
#define NT    (B*F)
#define G     30          // frames emitted per group
#define NGRP  (F/G)       // 100 groups per batch
#define WARM  8           // warm-up frames: contraction 0.97^(80*8) ~ 3e-9
#define DEPTH 4           // cp.async ring depth
#define SLOT  128         // floats: 16 zero | 80 h | 16 zero | 16 an

// Scratch (static device arrays -- allocation-free per harness rules)
__device__ __align__(16) static float g_h [(size_t)NT*80];   // impulse responses
__device__ __align__(16) static float g_w [(size_t)NT*80];   // zero-state responses
__device__ __align__(16) static float g_an[(size_t)NT*16];   // an[j] = -a'[j+1], j=0..15

// ---------------------------------------------------------------------------
// Kernel 1: 2*NT threads. First NT compute an + impulse response h (ring-32);
// second NT compute zero-state response w (ring-16).
// Combined filter: z[n] = e[n] + sum_j an[j] z[n-j],  an = -(a - EMPH*a_<<1).
// Ring indices written base-free ((16+u+k-j)&31 / (u+k-j)&15) so they are
// compile-time constants -> no local-memory demotion.
// ---------------------------------------------------------------------------
__global__ void __launch_bounds__(128) k_prep(const float* __restrict__ e,
                                              const float* __restrict__ lpc)
{
    int tid = blockIdx.x*128 + threadIdx.x;
    bool do_w = (tid >= NT);                 // uniform per block (NT % 128 == 0)
    int t2 = do_w ? tid - NT : tid;
    int b = t2 / F;
    int f = t2 - b*F;

    float av[16];
    const float4* a4 = reinterpret_cast<const float4*>(lpc + (size_t)t2*16);
#pragma unroll
    for (int j = 0; j < 4; j++) {
        float4 t = a4[j];
        av[4*j+0]=t.x; av[4*j+1]=t.y; av[4*j+2]=t.z; av[4*j+3]=t.w;
    }

    // an[j] = -a'[j],  a'_j = a_j - EMPH*a_{j-1}  (a_0 = 1, a_16 = 0)
    float an[17];
    an[1] = EMPH - av[1];
#pragma unroll
    for (int j = 2; j <= 15; j++) an[j] = EMPH*av[j-1] - av[j];
    an[16] = EMPH*av[15];

    if (!do_w) {
        // ---- h half: store an, compute h ----
        float4* anout = reinterpret_cast<float4*>(g_an + (size_t)t2*16);
#pragma unroll
        for (int j = 0; j < 16; j += 4)
            anout[j>>2] = make_float4(an[j+1], an[j+2], an[j+3], an[j+4]);

        float4* hout = reinterpret_cast<float4*>(g_h + (size_t)t2*80);
        float hr[32];

        hr[0] = 1.f;
#pragma unroll
        for (int m = 1; m < 16; m++) {
            float part = 0.f;
#pragma unroll
            for (int j = 2; j <= m; j++) part = fmaf(an[j], hr[m-j], part);
            hr[m] = fmaf(an[1], hr[m-1], part);
        }
#pragma unroll
        for (int m = 0; m < 16; m += 4)
            hout[m>>2] = make_float4(hr[m], hr[m+1], hr[m+2], hr[m+3]);

#pragma unroll 1
        for (int base = 16; base < 80; base += 32) {   // base ≡ 16 (mod 32)
#pragma unroll
            for (int u = 0; u < 32; u += 4) {
                float hb[4];
#pragma unroll
                for (int k = 0; k < 4; k++) {
                    int mi = 16 + u + k;               // static ring phase
                    float part = 0.f;
#pragma unroll
                    for (int j = 2; j <= 16; j++)
                        part = fmaf(an[j], hr[(mi - j) & 31], part);
                    float acch = fmaf(an[1], hr[(mi - 1) & 31], part);
                    hr[mi & 31] = acch;
                    hb[k] = acch;
                }
                hout[(base + u) >> 2] = make_float4(hb[0], hb[1], hb[2], hb[3]);
            }
        }
    } else {
        // ---- w half: zero-state response to this frame's excitation ----
        const float4* ef4 = reinterpret_cast<const float4*>(e + (size_t)b*L + (size_t)f*FSH);
        float4* wout = reinterpret_cast<float4*>(g_w + (size_t)t2*80);
        float wr[16];

#pragma unroll
        for (int m4 = 0; m4 < 16; m4 += 4) {
            float4 ev = ef4[m4 >> 2];
            float evl[4] = {ev.x, ev.y, ev.z, ev.w};
#pragma unroll
            for (int k = 0; k < 4; k++) {
                int m = m4 + k;
                float part = evl[k];
#pragma unroll
                for (int j = 2; j <= m; j++) part = fmaf(an[j], wr[m-j], part);
                wr[m] = (m >= 1) ? fmaf(an[1], wr[m-1], part) : part;
            }
        }
#pragma unroll
        for (int m = 0; m < 16; m += 4)
            wout[m>>2] = make_float4(wr[m], wr[m+1], wr[m+2], wr[m+3]);

#pragma unroll 1
        for (int base = 16; base < 80; base += 16) {   // base ≡ 0 (mod 16)
#pragma unroll
            for (int u = 0; u < 16; u += 4) {
                float4 ev = ef4[(base + u) >> 2];
                float evl[4] = {ev.x, ev.y, ev.z, ev.w};
                float wb[4];
#pragma unroll
                for (int k = 0; k < 4; k++) {
                    int mi = u + k;                    // static ring phase
                    float part = evl[k];
#pragma unroll
                    for (int j = 2; j <= 16; j++)
                        part = fmaf(an[j], wr[(mi - j) & 15], part);
                    float accw = fmaf(an[1], wr[(mi - 1) & 15], part);
                    wr[mi & 15] = accw;
                    wb[k] = accw;
                }
                wout[(base + u) >> 2] = make_float4(wb[0], wb[1], wb[2], wb[3]);
            }
        }
    }
}

// ---------------------------------------------------------------------------
// cp.async prefetch of one frame's h (80f) + an (16f) into a ring slot.
// slot floats: [0..16)=0 | [16..96)=h | [96..112)=0 | [112..128)=an
// ---------------------------------------------------------------------------
__device__ __forceinline__ void fused_prefetch(uint32_t slot, size_t fg, int lane, bool valid)
{
    if (valid) {
        if (lane < 20)
            asm volatile("cp.async.ca.shared.global [%0], [%1], 16;"
                         :: "r"(slot + 64u + (uint32_t)lane*16u),
                            "l"(g_h + fg*80 + lane*4) : "memory");
        if (lane < 4)
            asm volatile("cp.async.ca.shared.global [%0], [%1], 16;"
                         :: "r"(slot + 448u + (uint32_t)lane*16u),
                            "l"(g_an + fg*16 + lane*4) : "memory");
    }
    asm volatile("cp.async.commit_group;" ::: "memory");
}

// ---------------------------------------------------------------------------
// Kernel 2: fused scan + output. One warp per (batch, group of G frames),
// WARM warm-up frames from zero state (group 0 exact). Per frame:
//   r[k] = sum_{t<=15-k} an[k+t+1] s[t]   (split across lane halves + xor-16)
//   z[m] = w[m] + sum_k r[k] h[m-k]       (lane l -> m = l, l+32, l+64)
//   s_i' = z[79-i]
// w comes via coalesced LDG registers (distance-2 pipeline), h/an via cp.async.
// ---------------------------------------------------------------------------
__global__ void __launch_bounds__(256) k_fused(float* __restrict__ out)
{
    __shared__ __align__(16) float ring[8][DEPTH][SLOT];
    int w    = threadIdx.x >> 5;
    int lane = threadIdx.x & 31;
    size_t gg = (size_t)blockIdx.x*8 + w;
    int b = (int)(gg / NGRP), grp = (int)(gg - (size_t)b*NGRP);
    int f0 = grp * G;
    int fstart = (f0 >= WARM) ? f0 - WARM : 0;
    int warmcnt = f0 - fstart;
    int nfr = f0 + G - fstart;
    size_t fgbase = (size_t)b*F + fstart;
    uint32_t rbase = (uint32_t)__cvta_generic_to_shared(&ring[w][0][0]);

    // zero pads once (cp.async never touches them)
    if (lane < 16) {
#pragma unroll
        for (int k = 0; k < DEPTH; k++) {
            ring[w][k][lane]      = 0.f;
            ring[w][k][96 + lane] = 0.f;
        }
    }
    __syncwarp();

#pragma unroll
    for (int k = 0; k < DEPTH; k++)
        fused_prefetch(rbase + (uint32_t)k*SLOT*4u, fgbase + k, lane, k < nfr);

    // w pipeline: registers for frames j and j+1
    float wa0=0.f, wa1=0.f, wa2=0.f, wb0=0.f, wb1=0.f, wb2=0.f;
    {
        const float* wp = g_w + fgbase*80;
        wa0 = wp[lane]; wa1 = wp[lane+32];
        if (lane < 16) wa2 = wp[lane+64];
        if (1 < nfr) {
            wp += 80;
            wb0 = wp[lane]; wb1 = wp[lane+32];
            if (lane < 16) wb2 = wp[lane+64];
        }
    }

    float s = 0.f;                       // lane i<16 holds s_i = z_prev[79-i]
    float* outb = out + ((size_t)b*L + (size_t)fstart*FSH);
    int k16 = lane & 15;
    int tb  = (lane >> 4) << 3;          // 0 or 8

#pragma unroll 1
    for (int j = 0; j < nfr; j++) {
        asm volatile("cp.async.wait_group %0;" :: "n"(DEPTH-1) : "memory");
        __syncwarp();
        const float* slot = &ring[w][j & (DEPTH-1)][0];
        const float* h_s  = slot;          // h[m] at slot[m+16], pads zero
        const float* an_s = slot + 112;    // an_s[i] = an[i+1] = -a'[i+1]

        // prefetch w for frame j+2 into fresh registers
        float wc0=0.f, wc1=0.f, wc2=0.f;
        if (j + 2 < nfr) {
            const float* wp = g_w + (fgbase + j + 2)*80;
            wc0 = wp[lane]; wc1 = wp[lane+32];
            if (lane < 16) wc2 = wp[lane+64];
        }

        // r[k] split: low half t=0..7, high half t=8..15, combine via xor-16
        float part = 0.f;
#pragma unroll
        for (int t = 0; t < 8; t++) {
            int tt = tb + t;
            float sv = __shfl_sync(0xffffffffu, s, tt);
            int idx = k16 + tt; if (idx > 15) idx = 15;   // clamp keeps LDS in-slot
            if (tt <= 15 - k16) part = fmaf(an_s[idx], sv, part);
        }
        float r = part + __shfl_xor_sync(0xffffffffu, part, 16);

        // conv: z[m] = w[m] + sum_k r[k] h[m-k]
        float acc0 = 0.f, acc1 = 0.f, acc2 = 0.f;
#pragma unroll
        for (int k = 0; k < 16; k++) {
            float rk = __shfl_sync(0xffffffffu, r, k);
            acc0 = fmaf(rk, h_s[lane      - k + 16], acc0);
            acc1 = fmaf(rk, h_s[lane + 32 - k + 16], acc1);
            acc2 = fmaf(rk, h_s[lane + 64 - k + 16], acc2);
        }
        float z0 = acc0 + wa0;
        float z1 = acc1 + wa1;
        float z2 = acc2 + wa2;

        if (j >= warmcnt) {              // emit only the group's own frames
            float* ob = outb + (size_t)j*FSH;
            ob[lane]      = z0;
            ob[lane + 32] = z1;
            if (lane < 16) ob[lane + 64] = z2;
        }

        // next state: s_i = z[79-i] = z2 of lane (15-i)
        float ns = __shfl_sync(0xffffffffu, z2, (15 - lane) & 31);
        s = (lane < 16) ? ns : 0.f;

        wa0 = wb0; wa1 = wb1; wa2 = wb2;
        wb0 = wc0; wb1 = wc1; wb2 = wc2;

        __syncwarp();                    // all lanes done reading the slot
        fused_prefetch(rbase + (uint32_t)(j & (DEPTH-1))*SLOT*4u,
                       fgbase + j + DEPTH, lane, (j + DEPTH) < nfr);
    }
}

// ---------------------------------------------------------------------------
extern "C" void kernel_launch(void* const* d_in, const int* in_sizes, int n_in,
                              void* d_out, int out_size)
{
    (void)in_sizes; (void)n_in; (void)out_size;
    const float* e   = (const float*)d_in[0];   // excit (B, L, 1)
    const float* lpc = (const float*)d_in[1];   // lpc_coef (B, F, 16)
    float* out = (float*)d_out;                 // (B, L, 1)

    k_prep <<<(2*NT)/128, 128>>>(e, lpc);
    k_fused<<<(B*NGRP)/8, 256>>>(out);
}

// round 7
// speedup vs baseline: 5.4507x; 1.0969x over previous
#include <cuda_runtime.h>
#include <cstdint>

#define B     64
#define F     3000
#define FSH   80
#define L     240000
#define EMPH  0.97f
#define NT    (B*F)
#define G     30          // frames emitted per group
#define NGRP  (F/G)       // 100 groups per batch
#define WARM  8           // warm-up frames: contraction 0.97^(80*8) ~ 3e-9
#define DEPTH 4           // cp.async ring depth
#define SLOT  112         // floats: 15 zero | 80 h | 1 dontcare | 16 an

// Scratch (static device arrays -- allocation-free per harness rules)
__device__ __align__(16) static float g_h [(size_t)NT*80];   // impulse responses
__device__ __align__(16) static float g_w [(size_t)NT*80];   // zero-state responses
__device__ __align__(16) static float g_an[(size_t)NT*16];   // an[j] = -a'[j+1], j=0..15

// ---------------------------------------------------------------------------
// Kernel 1: 2*NT threads. First NT compute an + impulse response h (ring-32);
// second NT compute zero-state response w (ring-16).
// Combined filter: z[n] = e[n] + sum_j an[j] z[n-j],  an = -(a - EMPH*a_<<1).
// Ring indices are compile-time static -> no local-memory demotion.
// ---------------------------------------------------------------------------
__global__ void __launch_bounds__(128) k_prep(const float* __restrict__ e,
                                              const float* __restrict__ lpc)
{
    int tid = blockIdx.x*128 + threadIdx.x;
    bool do_w = (tid >= NT);                 // uniform per block (NT % 128 == 0)
    int t2 = do_w ? tid - NT : tid;
    int b = t2 / F;
    int f = t2 - b*F;

    float av[16];
    const float4* a4 = reinterpret_cast<const float4*>(lpc + (size_t)t2*16);
#pragma unroll
    for (int j = 0; j < 4; j++) {
        float4 t = a4[j];
        av[4*j+0]=t.x; av[4*j+1]=t.y; av[4*j+2]=t.z; av[4*j+3]=t.w;
    }

    // an[j] = -a'[j],  a'_j = a_j - EMPH*a_{j-1}  (a_0 = 1, a_16 = 0)
    float an[17];
    an[1] = EMPH - av[1];
#pragma unroll
    for (int j = 2; j <= 15; j++) an[j] = EMPH*av[j-1] - av[j];
    an[16] = EMPH*av[15];

    if (!do_w) {
        // ---- h half: store an, compute h ----
        float4* anout = reinterpret_cast<float4*>(g_an + (size_t)t2*16);
#pragma unroll
        for (int j = 0; j < 16; j += 4)
            anout[j>>2] = make_float4(an[j+1], an[j+2], an[j+3], an[j+4]);

        float4* hout = reinterpret_cast<float4*>(g_h + (size_t)t2*80);
        float hr[32];

        hr[0] = 1.f;
#pragma unroll
        for (int m = 1; m < 16; m++) {
            float part = 0.f;
#pragma unroll
            for (int j = 2; j <= m; j++) part = fmaf(an[j], hr[m-j], part);
            hr[m] = fmaf(an[1], hr[m-1], part);
        }
#pragma unroll
        for (int m = 0; m < 16; m += 4)
            hout[m>>2] = make_float4(hr[m], hr[m+1], hr[m+2], hr[m+3]);

#pragma unroll 1
        for (int base = 16; base < 80; base += 32) {   // base ≡ 16 (mod 32)
#pragma unroll
            for (int u = 0; u < 32; u += 4) {
                float hb[4];
#pragma unroll
                for (int k = 0; k < 4; k++) {
                    int mi = 16 + u + k;               // static ring phase
                    float part = 0.f;
#pragma unroll
                    for (int j = 2; j <= 16; j++)
                        part = fmaf(an[j], hr[(mi - j) & 31], part);
                    float acch = fmaf(an[1], hr[(mi - 1) & 31], part);
                    hr[mi & 31] = acch;
                    hb[k] = acch;
                }
                hout[(base + u) >> 2] = make_float4(hb[0], hb[1], hb[2], hb[3]);
            }
        }
    } else {
        // ---- w half: zero-state response to this frame's excitation ----
        const float4* ef4 = reinterpret_cast<const float4*>(e + (size_t)b*L + (size_t)f*FSH);
        float4* wout = reinterpret_cast<float4*>(g_w + (size_t)t2*80);
        float wr[16];

#pragma unroll
        for (int m4 = 0; m4 < 16; m4 += 4) {
            float4 ev = ef4[m4 >> 2];
            float evl[4] = {ev.x, ev.y, ev.z, ev.w};
#pragma unroll
            for (int k = 0; k < 4; k++) {
                int m = m4 + k;
                float part = evl[k];
#pragma unroll
                for (int j = 2; j <= m; j++) part = fmaf(an[j], wr[m-j], part);
                wr[m] = (m >= 1) ? fmaf(an[1], wr[m-1], part) : part;
            }
        }
#pragma unroll
        for (int m = 0; m < 16; m += 4)
            wout[m>>2] = make_float4(wr[m], wr[m+1], wr[m+2], wr[m+3]);

#pragma unroll 1
        for (int base = 16; base < 80; base += 16) {   // base ≡ 0 (mod 16)
#pragma unroll
            for (int u = 0; u < 16; u += 4) {
                float4 ev = ef4[(base + u) >> 2];
                float evl[4] = {ev.x, ev.y, ev.z, ev.w};
                float wb[4];
#pragma unroll
                for (int k = 0; k < 4; k++) {
                    int mi = u + k;                    // static ring phase
                    float part = evl[k];
#pragma unroll
                    for (int j = 2; j <= 16; j++)
                        part = fmaf(an[j], wr[(mi - j) & 15], part);
                    float accw = fmaf(an[1], wr[(mi - 1) & 15], part);
                    wr[mi & 15] = accw;
                    wb[k] = accw;
                }
                wout[(base + u) >> 2] = make_float4(wb[0], wb[1], wb[2], wb[3]);
            }
        }
    }
}

// ---------------------------------------------------------------------------
// cp.async prefetch of one frame's h (80f, 4B chunks into words 15..94) + an
// (16f, 16B chunks into words 96..111) into a ring slot.
// Words 0..14 are zero pads (written once); word 95 is never used in math.
// ---------------------------------------------------------------------------
__device__ __forceinline__ void fused_prefetch(uint32_t slot, size_t fg, int lane, bool valid)
{
    if (valid) {
        const float* hsrc = g_h + fg*80;
        asm volatile("cp.async.ca.shared.global [%0], [%1], 4;"
                     :: "r"(slot + (15u + (uint32_t)lane)*4u), "l"(hsrc + lane) : "memory");
        asm volatile("cp.async.ca.shared.global [%0], [%1], 4;"
                     :: "r"(slot + (47u + (uint32_t)lane)*4u), "l"(hsrc + lane + 32) : "memory");
        if (lane < 16)
            asm volatile("cp.async.ca.shared.global [%0], [%1], 4;"
                         :: "r"(slot + (79u + (uint32_t)lane)*4u), "l"(hsrc + lane + 64) : "memory");
        if (lane < 4)
            asm volatile("cp.async.ca.shared.global [%0], [%1], 16;"
                         :: "r"(slot + 384u + (uint32_t)lane*16u),
                            "l"(g_an + fg*16 + lane*4) : "memory");
    }
    asm volatile("cp.async.commit_group;" ::: "memory");
}

// ---------------------------------------------------------------------------
// Kernel 2: fused scan + output. One warp per (batch, group of G frames),
// WARM warm-up frames from zero state (group 0 exact). Lane l owns outputs
// m = 4l..4l+3 (lanes 0..19; lanes 20..31 shadow lane 19). Per frame:
//   r[k] = sum_{t<=15-k} an[k+t+1] s[t]    (shfl halves + xor-16), r -> smem
//   z[m] = w[m] + sum_k r[k] h[m-k]        (per k-quad: 2 aligned LDS.128 of h
//                                           window + 1 broadcast LDS.128 of r)
//   s_i' = z[79-i]                          (4 shfl + component select)
// w via LDG.128 distance-2 register pipeline; h/an via cp.async ring.
// ---------------------------------------------------------------------------
__global__ void __launch_bounds__(256) k_fused(float* __restrict__ out)
{
    __shared__ __align__(16) float ring[8][DEPTH][SLOT];
    __shared__ __align__(16) float rbuf[8][16];
    int w    = threadIdx.x >> 5;
    int lane = threadIdx.x & 31;
    size_t gg = (size_t)blockIdx.x*8 + w;
    int b = (int)(gg / NGRP), grp = (int)(gg - (size_t)b*NGRP);
    int f0 = grp * G;
    int fstart = (f0 >= WARM) ? f0 - WARM : 0;
    int warmcnt = f0 - fstart;
    int nfr = f0 + G - fstart;
    size_t fgbase = (size_t)b*F + fstart;
    uint32_t rbase = (uint32_t)__cvta_generic_to_shared(&ring[w][0][0]);
    float* rb = rbuf[w];

    // zero left pads once (cp.async never touches words 0..14)
    if (lane < 15) {
#pragma unroll
        for (int k = 0; k < DEPTH; k++) ring[w][k][lane] = 0.f;
    }
    __syncwarp();

#pragma unroll
    for (int k = 0; k < DEPTH; k++)
        fused_prefetch(rbase + (uint32_t)k*SLOT*4u, fgbase + k, lane, k < nfr);

    int lane2 = (lane < 20) ? lane : 19;

    // w pipeline: float4 for frames j and j+1
    float4 wa, wb;
    {
        const float4* wp = reinterpret_cast<const float4*>(g_w + fgbase*80) + lane2;
        wa = wp[0];
        wb = (1 < nfr) ? wp[20] : make_float4(0.f,0.f,0.f,0.f);
    }

    float s = 0.f;                       // lane i<16 holds s_i = z_prev[79-i]
    float* outb = out + ((size_t)b*L + (size_t)fstart*FSH);
    int k16 = lane & 15;
    int tb  = (lane >> 4) << 3;          // 0 or 8
    int src = 19 - (k16 >> 2);           // state-gather source lane
    int cm  = k16 & 3;

#pragma unroll 1
    for (int j = 0; j < nfr; j++) {
        asm volatile("cp.async.wait_group %0;" :: "n"(DEPTH-1) : "memory");
        __syncwarp();
        const float* slot = &ring[w][j & (DEPTH-1)][0];
        const float* an_s = slot + 96;     // an_s[i] = an[i+1] = -a'[i+1]

        // prefetch w for frame j+2
        float4 wc = make_float4(0.f,0.f,0.f,0.f);
        if (j + 2 < nfr)
            wc = reinterpret_cast<const float4*>(g_w + (fgbase + j + 2)*80)[lane2];

        // r[k] split: low half t=0..7, high half t=8..15, combine via xor-16
        float part = 0.f;
#pragma unroll
        for (int t = 0; t < 8; t++) {
            int tt = tb + t;
            float sv = __shfl_sync(0xffffffffu, s, tt);
            int idx = k16 + tt; if (idx > 15) idx = 15;   // clamp keeps LDS in-slot
            if (tt <= 15 - k16) part = fmaf(an_s[idx], sv, part);
        }
        float r = part + __shfl_xor_sync(0xffffffffu, part, 16);
        if (lane < 16) rb[lane] = r;
        __syncwarp();

        // conv: z[4l+c] = w + sum_k r[k] h[4l+c-k], k-quads via aligned LDS.128
        float a0 = wa.x, a1 = wa.y, a2 = wa.z, a3 = wa.w;
#pragma unroll
        for (int kg = 0; kg < 4; kg++) {
            const float4* hw = reinterpret_cast<const float4*>(slot + 4*lane2 - 4*kg + 12);
            float4 fa = hw[0];             // h[m0-4kg-3 .. m0-4kg]
            float4 fb = hw[1];             // h[m0-4kg+1 .. m0-4kg+4]
            float4 rq = reinterpret_cast<const float4*>(rb)[kg];  // broadcast
            a0 = fmaf(rq.x, fa.w, a0); a0 = fmaf(rq.y, fa.z, a0);
            a0 = fmaf(rq.z, fa.y, a0); a0 = fmaf(rq.w, fa.x, a0);
            a1 = fmaf(rq.x, fb.x, a1); a1 = fmaf(rq.y, fa.w, a1);
            a1 = fmaf(rq.z, fa.z, a1); a1 = fmaf(rq.w, fa.y, a1);
            a2 = fmaf(rq.x, fb.y, a2); a2 = fmaf(rq.y, fb.x, a2);
            a2 = fmaf(rq.z, fa.w, a2); a2 = fmaf(rq.w, fa.z, a2);
            a3 = fmaf(rq.x, fb.z, a3); a3 = fmaf(rq.y, fb.y, a3);
            a3 = fmaf(rq.z, fb.x, a3); a3 = fmaf(rq.w, fa.w, a3);
        }

        if (j >= warmcnt && lane < 20)     // emit only the group's own frames
            reinterpret_cast<float4*>(outb + (size_t)j*FSH)[lane] =
                make_float4(a0, a1, a2, a3);

        // next state: s_i = z[79-i]; z quads live on lanes 16..19
        float v0 = __shfl_sync(0xffffffffu, a0, src);
        float v1 = __shfl_sync(0xffffffffu, a1, src);
        float v2 = __shfl_sync(0xffffffffu, a2, src);
        float v3 = __shfl_sync(0xffffffffu, a3, src);
        float ns = (cm == 0) ? v3 : (cm == 1) ? v2 : (cm == 2) ? v1 : v0;
        s = (lane < 16) ? ns : 0.f;

        wa = wb; wb = wc;

        __syncwarp();                      // all lanes done reading the slot
        fused_prefetch(rbase + (uint32_t)(j & (DEPTH-1))*SLOT*4u,
                       fgbase + j + DEPTH, lane, (j + DEPTH) < nfr);
    }
}

// ---------------------------------------------------------------------------
extern "C" void kernel_launch(void* const* d_in, const int* in_sizes, int n_in,
                              void* d_out, int out_size)
{
    (void)in_sizes; (void)n_in; (void)out_size;
    const float* e   = (const float*)d_in[0];   // excit (B, L, 1)
    const float* lpc = (const float*)d_in[1];   // lpc_coef (B, F, 16)
    float* out = (float*)d_out;                 // (B, L, 1)

    k_prep <<<(2*NT)/128, 128>>>(e, lpc);
    k_fused<<<(B*NGRP)/8, 256>>>(out);
}

// round 8
// speedup vs baseline: 5.8534x; 1.0739x over previous
#include <cuda_runtime.h>
#include <cstdint>

#define B     64
#define F     3000
#define FSH   80
#define L     240000
#define EMPH  0.97f
#define NT    (B*F)
#define G     60          // frames emitted per group
#define NGRP  (F/G)       // 50 groups per batch -> 400 blocks = single wave
#define WARM  8           // warm-up frames: contraction 0.97^(80*8) ~ 3e-9
#define DEPTH 4           // cp.async ring depth
#define SLOT  128         // floats: 15 zero | 80 h | 1 junk | 16 an | 15 zero | 1 spare

// Scratch (static device arrays -- allocation-free per harness rules)
__device__ __align__(16) static float g_h [(size_t)NT*80];   // impulse responses
__device__ __align__(16) static float g_w [(size_t)NT*80];   // zero-state responses
__device__ __align__(16) static float g_an[(size_t)NT*16];   // an[j] = -a'[j+1], j=0..15

// ---------------------------------------------------------------------------
// Kernel 1: 2*NT threads. First NT compute an + impulse response h (ring-32);
// second NT compute zero-state response w (ring-16).
// Combined filter: z[n] = e[n] + sum_j an[j] z[n-j],  an = -(a - EMPH*a_<<1).
// Ring indices are compile-time static -> no local-memory demotion.
// ---------------------------------------------------------------------------
__global__ void __launch_bounds__(128) k_prep(const float* __restrict__ e,
                                              const float* __restrict__ lpc)
{
    int tid = blockIdx.x*128 + threadIdx.x;
    bool do_w = (tid >= NT);                 // uniform per block (NT % 128 == 0)
    int t2 = do_w ? tid - NT : tid;
    int b = t2 / F;
    int f = t2 - b*F;

    float av[16];
    const float4* a4 = reinterpret_cast<const float4*>(lpc + (size_t)t2*16);
#pragma unroll
    for (int j = 0; j < 4; j++) {
        float4 t = a4[j];
        av[4*j+0]=t.x; av[4*j+1]=t.y; av[4*j+2]=t.z; av[4*j+3]=t.w;
    }

    // an[j] = -a'[j],  a'_j = a_j - EMPH*a_{j-1}  (a_0 = 1, a_16 = 0)
    float an[17];
    an[1] = EMPH - av[1];
#pragma unroll
    for (int j = 2; j <= 15; j++) an[j] = EMPH*av[j-1] - av[j];
    an[16] = EMPH*av[15];

    if (!do_w) {
        // ---- h half: store an, compute h ----
        float4* anout = reinterpret_cast<float4*>(g_an + (size_t)t2*16);
#pragma unroll
        for (int j = 0; j < 16; j += 4)
            anout[j>>2] = make_float4(an[j+1], an[j+2], an[j+3], an[j+4]);

        float4* hout = reinterpret_cast<float4*>(g_h + (size_t)t2*80);
        float hr[32];

        hr[0] = 1.f;
#pragma unroll
        for (int m = 1; m < 16; m++) {
            float part = 0.f;
#pragma unroll
            for (int j = 2; j <= m; j++) part = fmaf(an[j], hr[m-j], part);
            hr[m] = fmaf(an[1], hr[m-1], part);
        }
#pragma unroll
        for (int m = 0; m < 16; m += 4)
            hout[m>>2] = make_float4(hr[m], hr[m+1], hr[m+2], hr[m+3]);

#pragma unroll 1
        for (int base = 16; base < 80; base += 32) {   // base ≡ 16 (mod 32)
#pragma unroll
            for (int u = 0; u < 32; u += 4) {
                float hb[4];
#pragma unroll
                for (int k = 0; k < 4; k++) {
                    int mi = 16 + u + k;               // static ring phase
                    float part = 0.f;
#pragma unroll
                    for (int j = 2; j <= 16; j++)
                        part = fmaf(an[j], hr[(mi - j) & 31], part);
                    float acch = fmaf(an[1], hr[(mi - 1) & 31], part);
                    hr[mi & 31] = acch;
                    hb[k] = acch;
                }
                hout[(base + u) >> 2] = make_float4(hb[0], hb[1], hb[2], hb[3]);
            }
        }
    } else {
        // ---- w half: zero-state response to this frame's excitation ----
        const float4* ef4 = reinterpret_cast<const float4*>(e + (size_t)b*L + (size_t)f*FSH);
        float4* wout = reinterpret_cast<float4*>(g_w + (size_t)t2*80);
        float wr[16];

#pragma unroll
        for (int m4 = 0; m4 < 16; m4 += 4) {
            float4 ev = ef4[m4 >> 2];
            float evl[4] = {ev.x, ev.y, ev.z, ev.w};
#pragma unroll
            for (int k = 0; k < 4; k++) {
                int m = m4 + k;
                float part = evl[k];
#pragma unroll
                for (int j = 2; j <= m; j++) part = fmaf(an[j], wr[m-j], part);
                wr[m] = (m >= 1) ? fmaf(an[1], wr[m-1], part) : part;
            }
        }
#pragma unroll
        for (int m = 0; m < 16; m += 4)
            wout[m>>2] = make_float4(wr[m], wr[m+1], wr[m+2], wr[m+3]);

#pragma unroll 1
        for (int base = 16; base < 80; base += 16) {   // base ≡ 0 (mod 16)
#pragma unroll
            for (int u = 0; u < 16; u += 4) {
                float4 ev = ef4[(base + u) >> 2];
                float evl[4] = {ev.x, ev.y, ev.z, ev.w};
                float wb[4];
#pragma unroll
                for (int k = 0; k < 4; k++) {
                    int mi = u + k;                    // static ring phase
                    float part = evl[k];
#pragma unroll
                    for (int j = 2; j <= 16; j++)
                        part = fmaf(an[j], wr[(mi - j) & 15], part);
                    float accw = fmaf(an[1], wr[(mi - 1) & 15], part);
                    wr[mi & 15] = accw;
                    wb[k] = accw;
                }
                wout[(base + u) >> 2] = make_float4(wb[0], wb[1], wb[2], wb[3]);
            }
        }
    }
}

// ---------------------------------------------------------------------------
// cp.async prefetch of one frame's h (80f, 4B chunks into words 15..94) + an
// (16f, 16B chunks into words 96..111) into a ring slot.
// Words 0..14 and 112..126 are zero pads (written once at init).
// ---------------------------------------------------------------------------
__device__ __forceinline__ void fused_prefetch(uint32_t slot, size_t fg, int lane, bool valid)
{
    if (valid) {
        const float* hsrc = g_h + fg*80;
        asm volatile("cp.async.ca.shared.global [%0], [%1], 4;"
                     :: "r"(slot + (15u + (uint32_t)lane)*4u), "l"(hsrc + lane) : "memory");
        asm volatile("cp.async.ca.shared.global [%0], [%1], 4;"
                     :: "r"(slot + (47u + (uint32_t)lane)*4u), "l"(hsrc + lane + 32) : "memory");
        if (lane < 16)
            asm volatile("cp.async.ca.shared.global [%0], [%1], 4;"
                         :: "r"(slot + (79u + (uint32_t)lane)*4u), "l"(hsrc + lane + 64) : "memory");
        if (lane < 4)
            asm volatile("cp.async.ca.shared.global [%0], [%1], 16;"
                         :: "r"(slot + 384u + (uint32_t)lane*16u),
                            "l"(g_an + fg*16 + lane*4) : "memory");
    }
    asm volatile("cp.async.commit_group;" ::: "memory");
}

// ---------------------------------------------------------------------------
// Kernel 2: fused scan + output. One warp per (batch, group of G frames),
// WARM warm-up frames from zero state (group 0 exact). Lane l owns outputs
// m = 4l..4l+3 (lanes 0..19; lanes 20..31 shadow lane 19). Per frame:
//   r[k] = sum_t an_s[k+t] s[t]   (zero-padded an: no clamp, no predicate)
//   z[m] = w[m] + sum_k r[k] h[m-k]  (5 shared float4 window loads, reused)
//   s_i' = z[79-i]                    (4 shfl + component select)
// w via LDG.128 distance-2 register pipeline; h/an via cp.async ring.
// ---------------------------------------------------------------------------
__global__ void __launch_bounds__(256) k_fused(float* __restrict__ out)
{
    __shared__ __align__(16) float ring[8][DEPTH][SLOT];
    __shared__ __align__(16) float rbuf[8][16];
    int w    = threadIdx.x >> 5;
    int lane = threadIdx.x & 31;
    size_t gg = (size_t)blockIdx.x*8 + w;
    int b = (int)(gg / NGRP), grp = (int)(gg - (size_t)b*NGRP);
    int f0 = grp * G;
    int fstart = (f0 >= WARM) ? f0 - WARM : 0;
    int warmcnt = f0 - fstart;
    int nfr = f0 + G - fstart;
    size_t fgbase = (size_t)b*F + fstart;
    uint32_t rbase = (uint32_t)__cvta_generic_to_shared(&ring[w][0][0]);
    float* rb = rbuf[w];

    // zero pads once: words 0..14 (left of h) and 112..126 (right of an)
    if (lane < 15) {
#pragma unroll
        for (int k = 0; k < DEPTH; k++) {
            ring[w][k][lane]       = 0.f;
            ring[w][k][112 + lane] = 0.f;
        }
    }
    __syncwarp();

#pragma unroll
    for (int k = 0; k < DEPTH; k++)
        fused_prefetch(rbase + (uint32_t)k*SLOT*4u, fgbase + k, lane, k < nfr);

    int lane2 = (lane < 20) ? lane : 19;

    // w pipeline: float4 for frames j and j+1
    float4 wa, wb;
    {
        const float4* wp = reinterpret_cast<const float4*>(g_w + fgbase*80) + lane2;
        wa = wp[0];
        wb = (1 < nfr) ? wp[20] : make_float4(0.f,0.f,0.f,0.f);
    }

    float s = 0.f;                       // lane i<16 holds s_i = z_prev[79-i]
    float* outb = out + ((size_t)b*L + (size_t)fstart*FSH);
    int k16 = lane & 15;
    int tb  = (lane >> 4) << 3;          // 0 or 8
    int src = 19 - (k16 >> 2);           // state-gather source lane
    int cm  = k16 & 3;

#pragma unroll 1
    for (int j = 0; j < nfr; j++) {
        asm volatile("cp.async.wait_group %0;" :: "n"(DEPTH-1) : "memory");
        __syncwarp();
        const float* slot = &ring[w][j & (DEPTH-1)][0];
        const float* an_s = slot + 96;     // an_s[i] = an[i+1]; [16..30] = 0

        // prefetch w for frame j+2
        float4 wc = make_float4(0.f,0.f,0.f,0.f);
        if (j + 2 < nfr)
            wc = reinterpret_cast<const float4*>(g_w + (fgbase + j + 2)*80)[lane2];

        // r[k]: halves t=0..7 / 8..15, combine via xor-16. Zero-padded an
        // region makes out-of-range taps contribute 0 -> no clamp/predicate.
        float part = 0.f;
#pragma unroll
        for (int t = 0; t < 8; t++) {
            int tt = tb + t;
            float sv = __shfl_sync(0xffffffffu, s, tt);
            part = fmaf(an_s[k16 + tt], sv, part);
        }
        float r = part + __shfl_xor_sync(0xffffffffu, part, 16);
        if (lane < 16) rb[lane] = r;
        __syncwarp();

        // conv: z[4l+c] = w + sum_k r[k] h[4l+c-k].
        // 5 overlapping float4 windows: q[i] = slot4[lane2+4-i];
        // fa(kg) = q[kg+1], fb(kg) = q[kg].
        const float4* slot4 = reinterpret_cast<const float4*>(slot);
        float4 q0 = slot4[lane2 + 4];
        float4 q1 = slot4[lane2 + 3];
        float4 q2 = slot4[lane2 + 2];
        float4 q3 = slot4[lane2 + 1];
        float4 q4 = slot4[lane2    ];

        float a0 = wa.x, a1 = wa.y, a2 = wa.z, a3 = wa.w;
        float4 qf[5] = {q0, q1, q2, q3, q4};
#pragma unroll
        for (int kg = 0; kg < 4; kg++) {
            float4 fb = qf[kg];
            float4 fa = qf[kg + 1];
            float4 rq = reinterpret_cast<const float4*>(rb)[kg];  // broadcast
            a0 = fmaf(rq.x, fa.w, a0); a0 = fmaf(rq.y, fa.z, a0);
            a0 = fmaf(rq.z, fa.y, a0); a0 = fmaf(rq.w, fa.x, a0);
            a1 = fmaf(rq.x, fb.x, a1); a1 = fmaf(rq.y, fa.w, a1);
            a1 = fmaf(rq.z, fa.z, a1); a1 = fmaf(rq.w, fa.y, a1);
            a2 = fmaf(rq.x, fb.y, a2); a2 = fmaf(rq.y, fb.x, a2);
            a2 = fmaf(rq.z, fa.w, a2); a2 = fmaf(rq.w, fa.z, a2);
            a3 = fmaf(rq.x, fb.z, a3); a3 = fmaf(rq.y, fb.y, a3);
            a3 = fmaf(rq.z, fb.x, a3); a3 = fmaf(rq.w, fa.w, a3);
        }

        if (j >= warmcnt && lane < 20)     // emit only the group's own frames
            reinterpret_cast<float4*>(outb + (size_t)j*FSH)[lane] =
                make_float4(a0, a1, a2, a3);

        // next state: s_i = z[79-i]; z quads live on lanes 16..19
        float v0 = __shfl_sync(0xffffffffu, a0, src);
        float v1 = __shfl_sync(0xffffffffu, a1, src);
        float v2 = __shfl_sync(0xffffffffu, a2, src);
        float v3 = __shfl_sync(0xffffffffu, a3, src);
        float ns = (cm == 0) ? v3 : (cm == 1) ? v2 : (cm == 2) ? v1 : v0;
        s = (lane < 16) ? ns : 0.f;

        wa = wb; wb = wc;

        __syncwarp();                      // all lanes done reading the slot
        fused_prefetch(rbase + (uint32_t)(j & (DEPTH-1))*SLOT*4u,
                       fgbase + j + DEPTH, lane, (j + DEPTH) < nfr);
    }
}

// ---------------------------------------------------------------------------
extern "C" void kernel_launch(void* const* d_in, const int* in_sizes, int n_in,
                              void* d_out, int out_size)
{
    (void)in_sizes; (void)n_in; (void)out_size;
    const float* e   = (const float*)d_in[0];   // excit (B, L, 1)
    const float* lpc = (const float*)d_in[1];   // lpc_coef (B, F, 16)
    float* out = (float*)d_out;                 // (B, L, 1)

    k_prep <<<(2*NT)/128, 128>>>(e, lpc);
    k_fused<<<(B*NGRP)/8, 256>>>(out);
}

// round 9
// speedup vs baseline: 6.4350x; 1.0994x over previous
#include <cuda_runtime.h>
#include <cstdint>

#define B     64
#define F     3000
#define FSH   80
#define L     240000
#define EMPH  0.97f
#define NT    (B*F)
#define G     50          // frames emitted per group
#define NGRP  (F/G)       // 60 groups per batch -> 480 blocks, single wave
#define WARM  5           // warm-up frames: 0.97^(80*5) ~ 5e-6 state error
#define DEPTH 4           // cp.async ring depth
#define SLOT  128         // floats: 15 zero | 80 h | 1 junk | 16 an | 15 zero | 1 spare

// Scratch (static device arrays -- allocation-free per harness rules)
__device__ __align__(16) static float g_h [(size_t)NT*80];   // impulse responses
__device__ __align__(16) static float g_w [(size_t)NT*80];   // zero-state responses
__device__ __align__(16) static float g_an[(size_t)NT*16];   // an[j] = -a'[j+1], j=0..15

// ---------------------------------------------------------------------------
// Kernel 1: 2*NT threads; first NT compute an + h, second NT compute w.
// A warp owns 32 CONSECUTIVE frames; all its global I/O spans are contiguous
// (frame t2's samples live at t2*80). Rows are staged in smem with stride 81:
//  - per-thread row access  buf[lane*81 + m]          -> conflict-free (81 odd)
//  - flat copy element i    buf[i + i/80]             -> ~conflict-free, and
//    global side is perfectly coalesced scalar LDG/STG.
// ---------------------------------------------------------------------------
__global__ void __launch_bounds__(128) k_prep(const float* __restrict__ e,
                                              const float* __restrict__ lpc)
{
    __shared__ float buf[4][32*81];
    int tid = blockIdx.x*128 + threadIdx.x;
    bool do_w = (tid >= NT);                 // uniform per block (NT % 128 == 0)
    int t2 = do_w ? tid - NT : tid;
    int wid  = threadIdx.x >> 5;
    int lane = threadIdx.x & 31;
    int wf0  = t2 - lane;                    // warp's first frame
    float* bw = buf[wid];

    float av[16];
    const float4* a4 = reinterpret_cast<const float4*>(lpc + (size_t)t2*16);
#pragma unroll
    for (int j = 0; j < 4; j++) {
        float4 t = a4[j];
        av[4*j+0]=t.x; av[4*j+1]=t.y; av[4*j+2]=t.z; av[4*j+3]=t.w;
    }

    // an[j] = -a'[j],  a'_j = a_j - EMPH*a_{j-1}  (a_0 = 1, a_16 = 0)
    float an[17];
    an[1] = EMPH - av[1];
#pragma unroll
    for (int j = 2; j <= 15; j++) an[j] = EMPH*av[j-1] - av[j];
    an[16] = EMPH*av[15];

    if (!do_w) {
        // ---- h half: store an, compute h into smem row ----
        float4* anout = reinterpret_cast<float4*>(g_an + (size_t)t2*16);
#pragma unroll
        for (int j = 0; j < 16; j += 4)
            anout[j>>2] = make_float4(an[j+1], an[j+2], an[j+3], an[j+4]);

        float* row = bw + lane*81;
        float hr[32];

        hr[0] = 1.f;
        row[0] = 1.f;
#pragma unroll
        for (int m = 1; m < 16; m++) {
            float part = 0.f;
#pragma unroll
            for (int j = 2; j <= m; j++) part = fmaf(an[j], hr[m-j], part);
            hr[m] = fmaf(an[1], hr[m-1], part);
            row[m] = hr[m];
        }
#pragma unroll 1
        for (int base = 16; base < 80; base += 32) {   // base ≡ 16 (mod 32)
#pragma unroll
            for (int u = 0; u < 32; u++) {
                int mi = 16 + u;                       // static ring phase
                float part = 0.f;
#pragma unroll
                for (int j = 2; j <= 16; j++)
                    part = fmaf(an[j], hr[(mi - j) & 31], part);
                float acch = fmaf(an[1], hr[(mi - 1) & 31], part);
                hr[mi & 31] = acch;
                row[base + u] = acch;
            }
        }
    } else {
        // ---- w half: coalesced e -> smem, in-place recursion e -> w ----
        const float* eg = e + (size_t)wf0*80;
#pragma unroll 8
        for (int it = 0; it < 80; it++) {
            int i = it*32 + lane;
            bw[i + i/80] = eg[i];                      // coalesced LDG.32
        }
        __syncwarp();

        float* row = bw + lane*81;
        float wr[16];
#pragma unroll
        for (int m = 0; m < 16; m++) {
            float part = row[m];
#pragma unroll
            for (int j = 2; j <= m; j++) part = fmaf(an[j], wr[m-j], part);
            wr[m] = (m >= 1) ? fmaf(an[1], wr[m-1], part) : part;
            row[m] = wr[m];
        }
#pragma unroll 1
        for (int base = 16; base < 80; base += 16) {   // base ≡ 0 (mod 16)
#pragma unroll
            for (int u = 0; u < 16; u++) {
                int mi = u;                            // static ring phase
                float part = row[base + u];
#pragma unroll
                for (int j = 2; j <= 16; j++)
                    part = fmaf(an[j], wr[(mi - j) & 15], part);
                float accw = fmaf(an[1], wr[(mi - 1) & 15], part);
                wr[mi & 15] = accw;
                row[base + u] = accw;
            }
        }
    }
    __syncwarp();

    // coalesced copy-out of the warp's 2560-float span
    float* dst = (do_w ? g_w : g_h) + (size_t)wf0*80;
#pragma unroll 8
    for (int it = 0; it < 80; it++) {
        int i = it*32 + lane;
        dst[i] = bw[i + i/80];                         // coalesced STG.32
    }
}

// ---------------------------------------------------------------------------
// cp.async prefetch of one frame's h (80f, 4B chunks into words 15..94) + an
// (16f, 16B chunks into words 96..111) into a ring slot.
// Words 0..14 and 112..126 are zero pads (written once at init).
// ---------------------------------------------------------------------------
__device__ __forceinline__ void fused_prefetch(uint32_t slot, size_t fg, int lane, bool valid)
{
    if (valid) {
        const float* hsrc = g_h + fg*80;
        asm volatile("cp.async.ca.shared.global [%0], [%1], 4;"
                     :: "r"(slot + (15u + (uint32_t)lane)*4u), "l"(hsrc + lane) : "memory");
        asm volatile("cp.async.ca.shared.global [%0], [%1], 4;"
                     :: "r"(slot + (47u + (uint32_t)lane)*4u), "l"(hsrc + lane + 32) : "memory");
        if (lane < 16)
            asm volatile("cp.async.ca.shared.global [%0], [%1], 4;"
                         :: "r"(slot + (79u + (uint32_t)lane)*4u), "l"(hsrc + lane + 64) : "memory");
        if (lane < 4)
            asm volatile("cp.async.ca.shared.global [%0], [%1], 16;"
                         :: "r"(slot + 384u + (uint32_t)lane*16u),
                            "l"(g_an + fg*16 + lane*4) : "memory");
    }
    asm volatile("cp.async.commit_group;" ::: "memory");
}

// ---------------------------------------------------------------------------
// Kernel 2: fused scan + output. One warp per (batch, group of G frames),
// WARM warm-up frames from zero state (group 0 exact). Lane l owns outputs
// m = 4l..4l+3 (lanes 0..19; lanes 20..31 shadow lane 19). Per frame:
//   r[k] = sum_t an_s[k+t] s[t]   (zero-padded an: no clamp, no predicate)
//   z[m] = w[m] + sum_k r[k] h[m-k]  (5 shared float4 window loads, reused)
//   s_i' = z[79-i]                    (4 shfl + component select)
// w via LDG.128 distance-2 register pipeline; h/an via cp.async ring.
// ---------------------------------------------------------------------------
__global__ void __launch_bounds__(256) k_fused(float* __restrict__ out)
{
    __shared__ __align__(16) float ring[8][DEPTH][SLOT];
    __shared__ __align__(16) float rbuf[8][16];
    int w    = threadIdx.x >> 5;
    int lane = threadIdx.x & 31;
    size_t gg = (size_t)blockIdx.x*8 + w;
    int b = (int)(gg / NGRP), grp = (int)(gg - (size_t)b*NGRP);
    int f0 = grp * G;
    int fstart = (f0 >= WARM) ? f0 - WARM : 0;
    int warmcnt = f0 - fstart;
    int nfr = f0 + G - fstart;
    size_t fgbase = (size_t)b*F + fstart;
    uint32_t rbase = (uint32_t)__cvta_generic_to_shared(&ring[w][0][0]);
    float* rb = rbuf[w];

    // zero pads once: words 0..14 (left of h) and 112..126 (right of an)
    if (lane < 15) {
#pragma unroll
        for (int k = 0; k < DEPTH; k++) {
            ring[w][k][lane]       = 0.f;
            ring[w][k][112 + lane] = 0.f;
        }
    }
    __syncwarp();

#pragma unroll
    for (int k = 0; k < DEPTH; k++)
        fused_prefetch(rbase + (uint32_t)k*SLOT*4u, fgbase + k, lane, k < nfr);

    int lane2 = (lane < 20) ? lane : 19;

    // w pipeline: float4 for frames j and j+1
    float4 wa, wb;
    {
        const float4* wp = reinterpret_cast<const float4*>(g_w + fgbase*80) + lane2;
        wa = wp[0];
        wb = (1 < nfr) ? wp[20] : make_float4(0.f,0.f,0.f,0.f);
    }

    float s = 0.f;                       // lane i<16 holds s_i = z_prev[79-i]
    float* outb = out + ((size_t)b*L + (size_t)fstart*FSH);
    int k16 = lane & 15;
    int tb  = (lane >> 4) << 3;          // 0 or 8
    int src = 19 - (k16 >> 2);           // state-gather source lane
    int cm  = k16 & 3;

#pragma unroll 1
    for (int j = 0; j < nfr; j++) {
        asm volatile("cp.async.wait_group %0;" :: "n"(DEPTH-1) : "memory");
        __syncwarp();
        const float* slot = &ring[w][j & (DEPTH-1)][0];
        const float* an_s = slot + 96;     // an_s[i] = an[i+1]; [16..30] = 0

        // prefetch w for frame j+2
        float4 wc = make_float4(0.f,0.f,0.f,0.f);
        if (j + 2 < nfr)
            wc = reinterpret_cast<const float4*>(g_w + (fgbase + j + 2)*80)[lane2];

        // r[k]: halves t=0..7 / 8..15, combine via xor-16. Zero-padded an
        // region makes out-of-range taps contribute 0 -> no clamp/predicate.
        float part = 0.f;
#pragma unroll
        for (int t = 0; t < 8; t++) {
            int tt = tb + t;
            float sv = __shfl_sync(0xffffffffu, s, tt);
            part = fmaf(an_s[k16 + tt], sv, part);
        }
        float r = part + __shfl_xor_sync(0xffffffffu, part, 16);
        if (lane < 16) rb[lane] = r;
        __syncwarp();

        // conv: z[4l+c] = w + sum_k r[k] h[4l+c-k].
        // 5 overlapping float4 windows: q[i] = slot4[lane2+4-i];
        // fa(kg) = q[kg+1], fb(kg) = q[kg].
        const float4* slot4 = reinterpret_cast<const float4*>(slot);
        float4 q0 = slot4[lane2 + 4];
        float4 q1 = slot4[lane2 + 3];
        float4 q2 = slot4[lane2 + 2];
        float4 q3 = slot4[lane2 + 1];
        float4 q4 = slot4[lane2    ];

        float a0 = wa.x, a1 = wa.y, a2 = wa.z, a3 = wa.w;
        float4 qf[5] = {q0, q1, q2, q3, q4};
#pragma unroll
        for (int kg = 0; kg < 4; kg++) {
            float4 fb = qf[kg];
            float4 fa = qf[kg + 1];
            float4 rq = reinterpret_cast<const float4*>(rb)[kg];  // broadcast
            a0 = fmaf(rq.x, fa.w, a0); a0 = fmaf(rq.y, fa.z, a0);
            a0 = fmaf(rq.z, fa.y, a0); a0 = fmaf(rq.w, fa.x, a0);
            a1 = fmaf(rq.x, fb.x, a1); a1 = fmaf(rq.y, fa.w, a1);
            a1 = fmaf(rq.z, fa.z, a1); a1 = fmaf(rq.w, fa.y, a1);
            a2 = fmaf(rq.x, fb.y, a2); a2 = fmaf(rq.y, fb.x, a2);
            a2 = fmaf(rq.z, fa.w, a2); a2 = fmaf(rq.w, fa.z, a2);
            a3 = fmaf(rq.x, fb.z, a3); a3 = fmaf(rq.y, fb.y, a3);
            a3 = fmaf(rq.z, fb.x, a3); a3 = fmaf(rq.w, fa.w, a3);
        }

        if (j >= warmcnt && lane < 20)     // emit only the group's own frames
            reinterpret_cast<float4*>(outb + (size_t)j*FSH)[lane] =
                make_float4(a0, a1, a2, a3);

        // next state: s_i = z[79-i]; z quads live on lanes 16..19
        float v0 = __shfl_sync(0xffffffffu, a0, src);
        float v1 = __shfl_sync(0xffffffffu, a1, src);
        float v2 = __shfl_sync(0xffffffffu, a2, src);
        float v3 = __shfl_sync(0xffffffffu, a3, src);
        float ns = (cm == 0) ? v3 : (cm == 1) ? v2 : (cm == 2) ? v1 : v0;
        s = (lane < 16) ? ns : 0.f;

        wa = wb; wb = wc;

        __syncwarp();                      // all lanes done reading the slot
        fused_prefetch(rbase + (uint32_t)(j & (DEPTH-1))*SLOT*4u,
                       fgbase + j + DEPTH, lane, (j + DEPTH) < nfr);
    }
}

// ---------------------------------------------------------------------------
extern "C" void kernel_launch(void* const* d_in, const int* in_sizes, int n_in,
                              void* d_out, int out_size)
{
    (void)in_sizes; (void)n_in; (void)out_size;
    const float* e   = (const float*)d_in[0];   // excit (B, L, 1)
    const float* lpc = (const float*)d_in[1];   // lpc_coef (B, F, 16)
    float* out = (float*)d_out;                 // (B, L, 1)

    k_prep <<<(2*NT)/128, 128>>>(e, lpc);
    k_fused<<<(B*NGRP)/8, 256>>>(out);
}

// round 10
// speedup vs baseline: 7.5451x; 1.1725x over previous
#include <cuda_runtime.h>
#include <cstdint>

#define B     64
#define F     3000
#define FSH   80
#define L     240000
#define EMPH  0.97f
#define NT    (B*F)
#define G     40          // frames emitted per group
#define NGRP  (F/G)       // 75 groups per batch -> 600 blocks, 4/SM resident
#define WARM  5           // warm-up frames: 0.97^(80*5) ~ 5e-6 state error
#define DEPTH 4           // cp.async ring depth
#define SLOT  128         // floats: 16 zero | 80 h | 16 an | 15 zero | 1 spare

// Scratch (static device arrays -- allocation-free per harness rules)
__device__ __align__(16) static float g_h [(size_t)NT*80];   // impulse responses
__device__ __align__(16) static float g_w [(size_t)NT*80];   // zero-state responses
__device__ __align__(16) static float g_an[(size_t)NT*16];   // an[j] = -a'[j+1], j=0..15

// ---------------------------------------------------------------------------
// Kernel 1: 2*NT threads; first NT compute an + h, second NT compute w.
// A warp owns 32 CONSECUTIVE frames; all its global I/O spans are contiguous
// (frame t2's samples live at t2*80). Rows are staged in smem with stride 81:
//  - per-thread row access  buf[lane*81 + m]          -> conflict-free (81 odd)
//  - flat copy element i    buf[i + i/80]             -> ~conflict-free, and
//    global side is perfectly coalesced scalar LDG/STG.
// ---------------------------------------------------------------------------
__global__ void __launch_bounds__(128) k_prep(const float* __restrict__ e,
                                              const float* __restrict__ lpc)
{
    __shared__ float buf[4][32*81];
    int tid = blockIdx.x*128 + threadIdx.x;
    bool do_w = (tid >= NT);                 // uniform per block (NT % 128 == 0)
    int t2 = do_w ? tid - NT : tid;
    int wid  = threadIdx.x >> 5;
    int lane = threadIdx.x & 31;
    int wf0  = t2 - lane;                    // warp's first frame
    float* bw = buf[wid];

    float av[16];
    const float4* a4 = reinterpret_cast<const float4*>(lpc + (size_t)t2*16);
#pragma unroll
    for (int j = 0; j < 4; j++) {
        float4 t = a4[j];
        av[4*j+0]=t.x; av[4*j+1]=t.y; av[4*j+2]=t.z; av[4*j+3]=t.w;
    }

    // an[j] = -a'[j],  a'_j = a_j - EMPH*a_{j-1}  (a_0 = 1, a_16 = 0)
    float an[17];
    an[1] = EMPH - av[1];
#pragma unroll
    for (int j = 2; j <= 15; j++) an[j] = EMPH*av[j-1] - av[j];
    an[16] = EMPH*av[15];

    if (!do_w) {
        // ---- h half: store an, compute h into smem row ----
        float4* anout = reinterpret_cast<float4*>(g_an + (size_t)t2*16);
#pragma unroll
        for (int j = 0; j < 16; j += 4)
            anout[j>>2] = make_float4(an[j+1], an[j+2], an[j+3], an[j+4]);

        float* row = bw + lane*81;
        float hr[32];

        hr[0] = 1.f;
        row[0] = 1.f;
#pragma unroll
        for (int m = 1; m < 16; m++) {
            float part = 0.f;
#pragma unroll
            for (int j = 2; j <= m; j++) part = fmaf(an[j], hr[m-j], part);
            hr[m] = fmaf(an[1], hr[m-1], part);
            row[m] = hr[m];
        }
#pragma unroll 1
        for (int base = 16; base < 80; base += 32) {   // base ≡ 16 (mod 32)
#pragma unroll
            for (int u = 0; u < 32; u++) {
                int mi = 16 + u;                       // static ring phase
                float part = 0.f;
#pragma unroll
                for (int j = 2; j <= 16; j++)
                    part = fmaf(an[j], hr[(mi - j) & 31], part);
                float acch = fmaf(an[1], hr[(mi - 1) & 31], part);
                hr[mi & 31] = acch;
                row[base + u] = acch;
            }
        }
    } else {
        // ---- w half: coalesced e -> smem, in-place recursion e -> w ----
        const float* eg = e + (size_t)wf0*80;
#pragma unroll 8
        for (int it = 0; it < 80; it++) {
            int i = it*32 + lane;
            bw[i + i/80] = eg[i];                      // coalesced LDG.32
        }
        __syncwarp();

        float* row = bw + lane*81;
        float wr[16];
#pragma unroll
        for (int m = 0; m < 16; m++) {
            float part = row[m];
#pragma unroll
            for (int j = 2; j <= m; j++) part = fmaf(an[j], wr[m-j], part);
            wr[m] = (m >= 1) ? fmaf(an[1], wr[m-1], part) : part;
            row[m] = wr[m];
        }
#pragma unroll 1
        for (int base = 16; base < 80; base += 16) {   // base ≡ 0 (mod 16)
#pragma unroll
            for (int u = 0; u < 16; u++) {
                int mi = u;                            // static ring phase
                float part = row[base + u];
#pragma unroll
                for (int j = 2; j <= 16; j++)
                    part = fmaf(an[j], wr[(mi - j) & 15], part);
                float accw = fmaf(an[1], wr[(mi - 1) & 15], part);
                wr[mi & 15] = accw;
                row[base + u] = accw;
            }
        }
    }
    __syncwarp();

    // coalesced copy-out of the warp's 2560-float span
    float* dst = (do_w ? g_w : g_h) + (size_t)wf0*80;
#pragma unroll 8
    for (int it = 0; it < 80; it++) {
        int i = it*32 + lane;
        dst[i] = bw[i + i/80];                         // coalesced STG.32
    }
}

// ---------------------------------------------------------------------------
// cp.async prefetch of one frame's h (80f, 16B chunks into words 16..95) + an
// (16f, 16B chunks into words 96..111) into a ring slot.
// Words 0..15 and 112..126 are zero pads (written once at init).
// ---------------------------------------------------------------------------
__device__ __forceinline__ void fused_prefetch(uint32_t slot, size_t fg, int lane, bool valid)
{
    if (valid) {
        if (lane < 20)
            asm volatile("cp.async.ca.shared.global [%0], [%1], 16;"
                         :: "r"(slot + 64u + (uint32_t)lane*16u),
                            "l"(g_h + fg*80 + lane*4) : "memory");
        if (lane < 4)
            asm volatile("cp.async.ca.shared.global [%0], [%1], 16;"
                         :: "r"(slot + 384u + (uint32_t)lane*16u),
                            "l"(g_an + fg*16 + lane*4) : "memory");
    }
    asm volatile("cp.async.commit_group;" ::: "memory");
}

// ---------------------------------------------------------------------------
// Kernel 2: fused scan + output. One warp per (batch, group of G frames),
// WARM warm-up frames from zero state (group 0 exact). Lane l owns outputs
// m = 4l..4l+3 (lanes 0..19; lanes 20..31 shadow lane 19). Shuffle-free loop:
//   state s[t] = z_prev[79-t] lives in per-warp smem rb[31-t]
//   r[k] = sum_t an_s[k+t] * rb[31-t]   (broadcast LDS, zero-padded an)
//   z[m] = w[m] + sum_k r[k] h[m-k]     (5 overlapping float4 windows)
//   lanes 16..19 store z[64..79] back to rb for the next frame
// w via LDG.128 distance-2 register pipeline; h/an via cp.async ring.
// ---------------------------------------------------------------------------
__global__ void __launch_bounds__(256, 4) k_fused(float* __restrict__ out)
{
    __shared__ __align__(16) float ring[8][DEPTH][SLOT];
    __shared__ __align__(16) float rbuf[8][32];   // [0..15] r | [16..31] z-tail
    int w    = threadIdx.x >> 5;
    int lane = threadIdx.x & 31;
    size_t gg = (size_t)blockIdx.x*8 + w;
    int b = (int)(gg / NGRP), grp = (int)(gg - (size_t)b*NGRP);
    int f0 = grp * G;
    int fstart = (f0 >= WARM) ? f0 - WARM : 0;
    int warmcnt = f0 - fstart;
    int nfr = f0 + G - fstart;
    size_t fgbase = (size_t)b*F + fstart;
    uint32_t rbase = (uint32_t)__cvta_generic_to_shared(&ring[w][0][0]);
    float* rb = rbuf[w];

    // zero pads once: words 0..15 (left of h) and 112..126 (right of an)
    if (lane < 16) {
#pragma unroll
        for (int k = 0; k < DEPTH; k++) {
            ring[w][k][lane] = 0.f;
            if (lane < 15) ring[w][k][112 + lane] = 0.f;
        }
        rb[16 + lane] = 0.f;                 // initial state z_prev = 0
    }
    __syncwarp();

#pragma unroll
    for (int k = 0; k < DEPTH; k++)
        fused_prefetch(rbase + (uint32_t)k*SLOT*4u, fgbase + k, lane, k < nfr);

    int lane2 = (lane < 20) ? lane : 19;

    // w pipeline: float4 for frames j and j+1
    float4 wa, wb;
    {
        const float4* wp = reinterpret_cast<const float4*>(g_w + fgbase*80) + lane2;
        wa = wp[0];
        wb = (1 < nfr) ? wp[20] : make_float4(0.f,0.f,0.f,0.f);
    }

    float* outb = out + ((size_t)b*L + (size_t)fstart*FSH);
    int k16 = lane & 15;
    int tb  = (lane >> 4) << 3;          // 0 or 8

#pragma unroll 1
    for (int j = 0; j < nfr; j++) {
        asm volatile("cp.async.wait_group %0;" :: "n"(DEPTH-1) : "memory");
        __syncwarp();
        const float* slot = &ring[w][j & (DEPTH-1)][0];
        const float* an_s = slot + 96;     // an_s[i] = an[i+1]; [16..30] = 0

        // prefetch w for frame j+2
        float4 wc = make_float4(0.f,0.f,0.f,0.f);
        if (j + 2 < nfr)
            wc = reinterpret_cast<const float4*>(g_w + (fgbase + j + 2)*80)[lane2];

        // r[k]: halves t=0..7 / 8..15, combine via xor-16. s[t] read straight
        // from smem (2-way broadcast); zero-padded an kills range predicates.
        float part = 0.f;
#pragma unroll
        for (int t = 0; t < 8; t++) {
            int tt = tb + t;
            part = fmaf(an_s[k16 + tt], rb[31 - tt], part);
        }
        float r = part + __shfl_xor_sync(0xffffffffu, part, 16);
        if (lane < 16) rb[lane] = r;
        __syncwarp();

        // conv: z[4l+c] = w + sum_k r[k] h[4l+c-k].
        // word(h[x]) = x+16; windows p_i = slot4[lane2+4-i]; for k-quad kg:
        // fb = p_kg, fa = p_{kg+1}; term(c,j) = rq[j]*(c>=j ? fb[c-j] : fa[4+c-j])
        const float4* slot4 = reinterpret_cast<const float4*>(slot);
        float4 qf[5];
        qf[0] = slot4[lane2 + 4];
        qf[1] = slot4[lane2 + 3];
        qf[2] = slot4[lane2 + 2];
        qf[3] = slot4[lane2 + 1];
        qf[4] = slot4[lane2    ];

        float a0 = wa.x, a1 = wa.y, a2 = wa.z, a3 = wa.w;
#pragma unroll
        for (int kg = 0; kg < 4; kg++) {
            float4 fb = qf[kg];
            float4 fa = qf[kg + 1];
            float4 rq = reinterpret_cast<const float4*>(rb)[kg];  // broadcast
            a0 = fmaf(rq.x, fb.x, a0); a0 = fmaf(rq.y, fa.w, a0);
            a0 = fmaf(rq.z, fa.z, a0); a0 = fmaf(rq.w, fa.y, a0);
            a1 = fmaf(rq.x, fb.y, a1); a1 = fmaf(rq.y, fb.x, a1);
            a1 = fmaf(rq.z, fa.w, a1); a1 = fmaf(rq.w, fa.z, a1);
            a2 = fmaf(rq.x, fb.z, a2); a2 = fmaf(rq.y, fb.y, a2);
            a2 = fmaf(rq.z, fb.x, a2); a2 = fmaf(rq.w, fa.w, a2);
            a3 = fmaf(rq.x, fb.w, a3); a3 = fmaf(rq.y, fb.z, a3);
            a3 = fmaf(rq.z, fb.y, a3); a3 = fmaf(rq.w, fb.x, a3);
        }

        if (j >= warmcnt && lane < 20)     // emit only the group's own frames
            reinterpret_cast<float4*>(outb + (size_t)j*FSH)[lane] =
                make_float4(a0, a1, a2, a3);

        // next state: lanes 16..19 hold z[64..79]; store z[4l+c] at rb[4l+c-48]
        if (lane >= 16 && lane < 20)
            reinterpret_cast<float4*>(rb + 16)[lane - 16] =
                make_float4(a0, a1, a2, a3);

        wa = wb; wb = wc;

        __syncwarp();                      // slot consumed + state published
        fused_prefetch(rbase + (uint32_t)(j & (DEPTH-1))*SLOT*4u,
                       fgbase + j + DEPTH, lane, (j + DEPTH) < nfr);
    }
}

// ---------------------------------------------------------------------------
extern "C" void kernel_launch(void* const* d_in, const int* in_sizes, int n_in,
                              void* d_out, int out_size)
{
    (void)in_sizes; (void)n_in; (void)out_size;
    const float* e   = (const float*)d_in[0];   // excit (B, L, 1)
    const float* lpc = (const float*)d_in[1];   // lpc_coef (B, F, 16)
    float* out = (float*)d_out;                 // (B, L, 1)

    k_prep <<<(2*NT)/128, 128>>>(e, lpc);
    k_fused<<<(B*NGRP)/8, 256>>>(out);
}